// round 1
// baseline (speedup 1.0000x reference)
#include <cuda_runtime.h>
#include <cuda_bf16.h>
#include <mma.h>

using namespace nvcuda;

#define DIM_   3072
#define S_TOT  1536
#define S_TXT_ 512
#define BATCH  2
#define HD_    128
#define HEADS_ 24
#define SCALE_ 0.08838834764831845f   // 1/sqrt(128)

#define JOINT_ELEMS (BATCH * S_TOT * DIM_)   // 9,437,184

// Scratch (no allocations allowed) — joint-layout Q/K/V and attention output.
__device__ float g_qj[JOINT_ELEMS];
__device__ float g_kj[JOINT_ELEMS];
__device__ float g_vj[JOINT_ELEMS];
__device__ float g_oj[JOINT_ELEMS];

// ---------------------------------------------------------------------------
// Generic TF32 GEMM: C[remap_out(m)][n] = sum_k A[remap_in(m)][k] * W[k][n] + bias[n]
// K = N = 3072 fixed. Tiles: BM=64, BN=64, BK=16. 128 threads (4 warps, 2x2 warp grid).
// remap(m; rpb, bsr, off) = (m/rpb)*bsr + off + (m%rpb)
// ---------------------------------------------------------------------------
__global__ void __launch_bounds__(128) gemm_tf32(
    const float* __restrict__ A, int in_rpb, int in_bsr, int in_off,
    const float* __restrict__ W, const float* __restrict__ bias,
    float* __restrict__ C, int out_rpb, int out_bsr, int out_off)
{
    __shared__ float As[64 * 16];
    __shared__ float Bs[16 * 64];
    __shared__ float Cs[64 * 64];

    const int tid  = threadIdx.x;
    const int warp = tid >> 5;
    const int wm   = warp >> 1;     // 0..1
    const int wn   = warp & 1;      // 0..1
    const int m0   = blockIdx.y * 64;
    const int n0   = blockIdx.x * 64;

    wmma::fragment<wmma::accumulator, 16, 16, 8, float> cf[2][2];
    #pragma unroll
    for (int i = 0; i < 2; i++)
        #pragma unroll
        for (int j = 0; j < 2; j++)
            wmma::fill_fragment(cf[i][j], 0.0f);

    for (int k0 = 0; k0 < DIM_; k0 += 16) {
        // Load A tile (64x16): 256 float4, 2 per thread
        #pragma unroll
        for (int it = 0; it < 2; it++) {
            int idx = tid + it * 128;
            int r = idx >> 2, c4 = idx & 3;
            int m = m0 + r;
            int in_row = (m / in_rpb) * in_bsr + in_off + (m % in_rpb);
            *(float4*)&As[r * 16 + c4 * 4] =
                *(const float4*)&A[(size_t)in_row * DIM_ + k0 + c4 * 4];
        }
        // Load W tile (16x64): 256 float4, 2 per thread
        #pragma unroll
        for (int it = 0; it < 2; it++) {
            int idx = tid + it * 128;
            int r = idx >> 4, c4 = idx & 15;
            *(float4*)&Bs[r * 64 + c4 * 4] =
                *(const float4*)&W[(size_t)(k0 + r) * DIM_ + n0 + c4 * 4];
        }
        __syncthreads();

        #pragma unroll
        for (int kk = 0; kk < 16; kk += 8) {
            wmma::fragment<wmma::matrix_a, 16, 16, 8, wmma::precision::tf32, wmma::row_major> af[2];
            wmma::fragment<wmma::matrix_b, 16, 16, 8, wmma::precision::tf32, wmma::row_major> bf[2];
            #pragma unroll
            for (int i = 0; i < 2; i++) {
                wmma::load_matrix_sync(af[i], &As[(wm * 32 + i * 16) * 16 + kk], 16);
                #pragma unroll
                for (int e = 0; e < af[i].num_elements; e++)
                    af[i].x[e] = wmma::__float_to_tf32(af[i].x[e]);
            }
            #pragma unroll
            for (int j = 0; j < 2; j++) {
                wmma::load_matrix_sync(bf[j], &Bs[kk * 64 + wn * 32 + j * 16], 64);
                #pragma unroll
                for (int e = 0; e < bf[j].num_elements; e++)
                    bf[j].x[e] = wmma::__float_to_tf32(bf[j].x[e]);
            }
            #pragma unroll
            for (int i = 0; i < 2; i++)
                #pragma unroll
                for (int j = 0; j < 2; j++)
                    wmma::mma_sync(cf[i][j], af[i], bf[j], cf[i][j]);
        }
        __syncthreads();
    }

    // Epilogue: stage to smem, add bias, remapped store
    #pragma unroll
    for (int i = 0; i < 2; i++)
        #pragma unroll
        for (int j = 0; j < 2; j++)
            wmma::store_matrix_sync(&Cs[(wm * 32 + i * 16) * 64 + wn * 32 + j * 16],
                                    cf[i][j], 64, wmma::mem_row_major);
    __syncthreads();

    #pragma unroll
    for (int it = 0; it < 8; it++) {
        int idx4 = tid + it * 128;      // 0..1023 float4s
        int r = idx4 >> 4, c4 = idx4 & 15;
        int m = m0 + r;
        int out_row = (m / out_rpb) * out_bsr + out_off + (m % out_rpb);
        float4 v = *(float4*)&Cs[r * 64 + c4 * 4];
        float4 bb = *(const float4*)&bias[n0 + c4 * 4];
        v.x += bb.x; v.y += bb.y; v.z += bb.z; v.w += bb.w;
        *(float4*)&C[(size_t)out_row * DIM_ + n0 + c4 * 4] = v;
    }
}

// ---------------------------------------------------------------------------
// Fused RMSNorm + RoPE, in-place on joint Q (z=0) and K (z=1).
// grid (S_TOT, BATCH, 2), 128 threads = 4 warps; each warp handles heads warp,warp+4,...
// ---------------------------------------------------------------------------
__global__ void __launch_bounds__(128) rms_rope_kernel(
    float* __restrict__ q, float* __restrict__ k,
    const float* __restrict__ cosr, const float* __restrict__ sinr,
    const float* __restrict__ gq, const float* __restrict__ gk,
    const float* __restrict__ gqc, const float* __restrict__ gkc)
{
    const int j = blockIdx.x, b = blockIdx.y, which = blockIdx.z;
    float* buf = which ? k : q;
    const float* g = which ? (j < S_TXT_ ? gkc : gk)
                           : (j < S_TXT_ ? gqc : gq);
    const int lane = threadIdx.x & 31;
    const int warp = threadIdx.x >> 5;
    const size_t rowbase = ((size_t)(b * S_TOT + j)) * DIM_;

    const float c0 = cosr[j * 64 + lane];
    const float s0 = sinr[j * 64 + lane];
    const float c1 = cosr[j * 64 + lane + 32];
    const float s1 = sinr[j * 64 + lane + 32];

    for (int h = warp; h < HEADS_; h += 4) {
        float* p = buf + rowbase + h * HD_;
        float2 e0 = *(float2*)&p[2 * lane];
        float2 e1 = *(float2*)&p[2 * (lane + 32)];
        float ss = e0.x * e0.x + e0.y * e0.y + e1.x * e1.x + e1.y * e1.y;
        #pragma unroll
        for (int o = 16; o; o >>= 1) ss += __shfl_xor_sync(0xffffffffu, ss, o);
        float inv = rsqrtf(ss * (1.0f / 128.0f) + 1e-6f);

        float x1 = e0.x * inv * g[2 * lane];
        float x2 = e0.y * inv * g[2 * lane + 1];
        float y1 = e1.x * inv * g[2 * (lane + 32)];
        float y2 = e1.y * inv * g[2 * (lane + 32) + 1];

        float2 o0 = make_float2(x1 * c0 - x2 * s0, x1 * s0 + x2 * c0);
        float2 o1 = make_float2(y1 * c1 - y2 * s1, y1 * s1 + y2 * c1);
        *(float2*)&p[2 * lane] = o0;
        *(float2*)&p[2 * (lane + 32)] = o1;
    }
}

// ---------------------------------------------------------------------------
// Flash-style attention. grid (S_TOT/64, HEADS, BATCH), 128 threads (4 warps).
// Each CTA: 64 q-rows of one (b,h). Loops over 12 K/V tiles of 128 keys.
// smem: K[128x128] V[128x128] P[64x128] O[64x128] + m/l stats.
// ---------------------------------------------------------------------------
#define ATTN_SMEM_BYTES ((16384 + 16384 + 8192 + 8192 + 128 + 64) * 4)

__global__ void __launch_bounds__(128) attn_kernel(
    const float* __restrict__ qj, const float* __restrict__ kj,
    const float* __restrict__ vj, float* __restrict__ oj)
{
    extern __shared__ float sm[];
    float* Ks   = sm;                 // 128*128
    float* Vs   = sm + 16384;         // 128*128
    float* Ps   = sm + 32768;         // 64*128 (Q staging, then scores/P)
    float* Os   = sm + 40960;         // 64*128
    float* mrow = sm + 49152;         // 64
    float* lrow = sm + 49216;         // 64

    const int tid  = threadIdx.x;
    const int warp = tid >> 5;
    const int q0   = blockIdx.x * 64;
    const int h    = blockIdx.y;
    const int b    = blockIdx.z;
    const size_t hd0 = (size_t)h * HD_;

    // Stage Q tile into Ps
    #pragma unroll
    for (int it = 0; it < 16; it++) {
        int idx4 = tid + it * 128;    // 0..2047
        int r = idx4 >> 5, c4 = idx4 & 31;
        size_t gaddr = ((size_t)(b * S_TOT + q0 + r)) * DIM_ + hd0 + c4 * 4;
        *(float4*)&Ps[r * 128 + c4 * 4] = *(const float4*)&qj[gaddr];
    }
    // Init O and stats
    #pragma unroll
    for (int it = 0; it < 16; it++)
        ((float4*)Os)[tid + it * 128] = make_float4(0.f, 0.f, 0.f, 0.f);
    if (tid < 64) { mrow[tid] = -1e30f; lrow[tid] = 0.f; }
    __syncthreads();

    // Preload Q fragments (16 d-chunks of 8) for this warp's 16 rows
    wmma::fragment<wmma::matrix_a, 16, 16, 8, wmma::precision::tf32, wmma::row_major> qf[16];
    #pragma unroll
    for (int t = 0; t < 16; t++) {
        wmma::load_matrix_sync(qf[t], &Ps[(warp * 16) * 128 + t * 8], 128);
        #pragma unroll
        for (int e = 0; e < qf[t].num_elements; e++)
            qf[t].x[e] = wmma::__float_to_tf32(qf[t].x[e]);
    }
    __syncthreads();  // Ps will be reused for scores

    for (int kt = 0; kt < S_TOT; kt += 128) {
        // Load K and V tiles (each 128x128)
        #pragma unroll
        for (int it = 0; it < 32; it++) {
            int idx4 = tid + it * 128;   // 0..4095
            int r = idx4 >> 5, c4 = idx4 & 31;
            size_t gaddr = ((size_t)(b * S_TOT + kt + r)) * DIM_ + hd0 + c4 * 4;
            *(float4*)&Ks[r * 128 + c4 * 4] = *(const float4*)&kj[gaddr];
            *(float4*)&Vs[r * 128 + c4 * 4] = *(const float4*)&vj[gaddr];
        }
        __syncthreads();

        // Scores: S[16q x 128k] per warp = Q @ K^T
        #pragma unroll
        for (int n = 0; n < 8; n++) {
            wmma::fragment<wmma::accumulator, 16, 16, 8, float> cf;
            wmma::fill_fragment(cf, 0.0f);
            #pragma unroll
            for (int kk = 0; kk < 16; kk++) {
                wmma::fragment<wmma::matrix_b, 16, 16, 8, wmma::precision::tf32, wmma::col_major> bf;
                wmma::load_matrix_sync(bf, &Ks[(n * 16) * 128 + kk * 8], 128);
                #pragma unroll
                for (int e = 0; e < bf.num_elements; e++)
                    bf.x[e] = wmma::__float_to_tf32(bf.x[e]);
                wmma::mma_sync(cf, qf[kk], bf, cf);
            }
            wmma::store_matrix_sync(&Ps[(warp * 16) * 128 + n * 16], cf, 128, wmma::mem_row_major);
        }
        __syncthreads();

        // Online softmax: one thread per q-row
        if (tid < 64) {
            const int r = tid;
            float mx = -1e30f;
            #pragma unroll 4
            for (int c = 0; c < 128; c++)
                mx = fmaxf(mx, Ps[r * 128 + c] * SCALE_);
            float newm = fmaxf(mrow[r], mx);
            float f = __expf(mrow[r] - newm);
            float sum = 0.f;
            #pragma unroll 4
            for (int c = 0; c < 128; c++) {
                float p = __expf(Ps[r * 128 + c] * SCALE_ - newm);
                Ps[r * 128 + c] = p;
                sum += p;
            }
            lrow[r] = lrow[r] * f + sum;
            mrow[r] = newm;
            #pragma unroll 4
            for (int c = 0; c < 128; c++)
                Os[r * 128 + c] *= f;
        }
        __syncthreads();

        // PV: O[16q x 128d] += P[16q x 128k] @ V[128k x 128d]
        #pragma unroll
        for (int n = 0; n < 8; n++) {
            wmma::fragment<wmma::accumulator, 16, 16, 8, float> cf;
            wmma::load_matrix_sync(cf, &Os[(warp * 16) * 128 + n * 16], 128, wmma::mem_row_major);
            #pragma unroll
            for (int kk = 0; kk < 16; kk++) {
                wmma::fragment<wmma::matrix_a, 16, 16, 8, wmma::precision::tf32, wmma::row_major> af;
                wmma::load_matrix_sync(af, &Ps[(warp * 16) * 128 + kk * 8], 128);
                #pragma unroll
                for (int e = 0; e < af.num_elements; e++)
                    af.x[e] = wmma::__float_to_tf32(af.x[e]);
                wmma::fragment<wmma::matrix_b, 16, 16, 8, wmma::precision::tf32, wmma::row_major> bf;
                wmma::load_matrix_sync(bf, &Vs[(kk * 8) * 128 + n * 16], 128);
                #pragma unroll
                for (int e = 0; e < bf.num_elements; e++)
                    bf.x[e] = wmma::__float_to_tf32(bf.x[e]);
                wmma::mma_sync(cf, af, bf, cf);
            }
            wmma::store_matrix_sync(&Os[(warp * 16) * 128 + n * 16], cf, 128, wmma::mem_row_major);
        }
        __syncthreads();
    }

    // Writeout: O / l
    #pragma unroll
    for (int it = 0; it < 16; it++) {
        int idx4 = tid + it * 128;
        int r = idx4 >> 5, c4 = idx4 & 31;
        float inv = 1.0f / lrow[r];
        float4 v = *(float4*)&Os[r * 128 + c4 * 4];
        v.x *= inv; v.y *= inv; v.z *= inv; v.w *= inv;
        size_t gaddr = ((size_t)(b * S_TOT + q0 + r)) * DIM_ + hd0 + c4 * 4;
        *(float4*)&oj[gaddr] = v;
    }
}

// ---------------------------------------------------------------------------
extern "C" void kernel_launch(void* const* d_in, const int* in_sizes, int n_in,
                              void* d_out, int out_size)
{
    const float* x    = (const float*)d_in[0];
    const float* ctx  = (const float*)d_in[1];
    const float* cosr = (const float*)d_in[2];
    const float* sinr = (const float*)d_in[3];
    const float* wq   = (const float*)d_in[4];
    const float* bq   = (const float*)d_in[5];
    const float* wk   = (const float*)d_in[6];
    const float* bk   = (const float*)d_in[7];
    const float* wv   = (const float*)d_in[8];
    const float* bv   = (const float*)d_in[9];
    const float* wqc  = (const float*)d_in[10];
    const float* bqc  = (const float*)d_in[11];
    const float* wkc  = (const float*)d_in[12];
    const float* bkc  = (const float*)d_in[13];
    const float* wvc  = (const float*)d_in[14];
    const float* bvc  = (const float*)d_in[15];
    const float* w_out     = (const float*)d_in[16];
    const float* b_out     = (const float*)d_in[17];
    const float* w_add_out = (const float*)d_in[18];
    const float* b_add_out = (const float*)d_in[19];
    const float* gq  = (const float*)d_in[20];
    const float* gk  = (const float*)d_in[21];
    const float* gqc = (const float*)d_in[22];
    const float* gkc = (const float*)d_in[23];
    float* out = (float*)d_out;

    float *qj, *kj, *vj, *oj;
    cudaGetSymbolAddress((void**)&qj, g_qj);
    cudaGetSymbolAddress((void**)&kj, g_kj);
    cudaGetSymbolAddress((void**)&vj, g_vj);
    cudaGetSymbolAddress((void**)&oj, g_oj);

    cudaFuncSetAttribute(attn_kernel, cudaFuncAttributeMaxDynamicSharedMemorySize,
                         ATTN_SMEM_BYTES);

    const dim3 blk(128);
    // QKV projections for x (M=2048) -> joint rows b*1536 + 512 + s
    gemm_tf32<<<dim3(48, 32), blk>>>(x, 2048, 2048, 0, wq, bq, qj, 1024, 1536, 512);
    gemm_tf32<<<dim3(48, 32), blk>>>(x, 2048, 2048, 0, wk, bk, kj, 1024, 1536, 512);
    gemm_tf32<<<dim3(48, 32), blk>>>(x, 2048, 2048, 0, wv, bv, vj, 1024, 1536, 512);
    // QKV projections for ctx (M=1024) -> joint rows b*1536 + s
    gemm_tf32<<<dim3(48, 16), blk>>>(ctx, 1024, 1024, 0, wqc, bqc, qj, 512, 1536, 0);
    gemm_tf32<<<dim3(48, 16), blk>>>(ctx, 1024, 1024, 0, wkc, bkc, kj, 512, 1536, 0);
    gemm_tf32<<<dim3(48, 16), blk>>>(ctx, 1024, 1024, 0, wvc, bvc, vj, 512, 1536, 0);

    // RMS norm + RoPE in-place on joint Q and K
    rms_rope_kernel<<<dim3(S_TOT, BATCH, 2), blk>>>(qj, kj, cosr, sinr, gq, gk, gqc, gkc);

    // Attention -> oj (joint layout)
    attn_kernel<<<dim3(S_TOT / 64, HEADS_, BATCH), blk, ATTN_SMEM_BYTES>>>(qj, kj, vj, oj);

    // Output projections: txt rows (j<512) -> d_out[0:], img rows -> d_out[2*512*3072:]
    gemm_tf32<<<dim3(48, 16), blk>>>(oj, 512, 1536, 0, w_add_out, b_add_out,
                                     out, 1024, 1024, 0);
    gemm_tf32<<<dim3(48, 32), blk>>>(oj, 1024, 1536, 512, w_out, b_out,
                                     out + (size_t)BATCH * S_TXT_ * DIM_, 2048, 2048, 0);
}

// round 4
// speedup vs baseline: 1.5818x; 1.5818x over previous
#include <cstdint>
#include <cuda_runtime.h>
#include <cuda_bf16.h>
#include <mma.h>

using namespace nvcuda;

#define DIM_   3072
#define S_TOT  1536
#define S_TXT_ 512
#define BATCH  2
#define HD_    128
#define HEADS_ 24
#define SCALE_ 0.08838834764831845f   // 1/sqrt(128)

#define JOINT_ELEMS (BATCH * S_TOT * DIM_)   // 9,437,184

// Scratch (no allocations allowed) — joint-layout Q/K/V and attention output.
__device__ float g_qj[JOINT_ELEMS];
__device__ float g_kj[JOINT_ELEMS];
__device__ float g_vj[JOINT_ELEMS];
__device__ float g_oj[JOINT_ELEMS];

__device__ __forceinline__ void cp_async16(void* smem_dst, const void* gmem_src) {
    unsigned int d = (unsigned int)__cvta_generic_to_shared(smem_dst);
    asm volatile("cp.async.cg.shared.global [%0], [%1], 16;\n" :: "r"(d), "l"(gmem_src));
}

// ---------------------------------------------------------------------------
// TF32 GEMM v2: BM=128, BN=128, BK=32, 256 threads (8 warps, 2x4 warp grid,
// warp tile 64x32). cp.async double-buffered. Row remap folded in (all rpb
// are multiples of 128, so remap is a per-CTA constant offset).
// Dynamic smem: As 2*128*36 + Bs 2*32*132 = 17664 floats = 70656 B.
// ---------------------------------------------------------------------------
#define GEMM_SMEM_BYTES (17664 * 4)

__global__ void __launch_bounds__(256, 2) gemm_tf32(
    const float* __restrict__ A, int in_rpb, int in_bsr, int in_off,
    const float* __restrict__ W, const float* __restrict__ bias,
    float* __restrict__ C, int out_rpb, int out_bsr, int out_off)
{
    extern __shared__ float sm[];
    float* As = sm;                 // 2 buffers of 128*36
    float* Bs = sm + 2 * 128 * 36;  // 2 buffers of 32*132

    const int tid  = threadIdx.x;
    const int warp = tid >> 5;
    const int wm   = warp >> 2;     // 0..1 : row block of 64
    const int wn   = warp & 3;      // 0..3 : col block of 32
    const int m0   = blockIdx.y * 128;
    const int n0   = blockIdx.x * 128;
    const int in_base  = (m0 / in_rpb) * in_bsr + in_off + (m0 % in_rpb);
    const int out_base = (m0 / out_rpb) * out_bsr + out_off + (m0 % out_rpb);

    wmma::fragment<wmma::accumulator, 16, 16, 8, float> cf[4][2];
    #pragma unroll
    for (int i = 0; i < 4; i++)
        #pragma unroll
        for (int j = 0; j < 2; j++)
            wmma::fill_fragment(cf[i][j], 0.0f);

    // ---- prefetch of one BK=32 tile into buffer bufi ----
    #define GEMM_PREFETCH(k0, bufi) do {                                          \
        float* Ad = As + (bufi) * (128 * 36);                                     \
        float* Bd = Bs + (bufi) * (32 * 132);                                     \
        _Pragma("unroll")                                                         \
        for (int it = 0; it < 4; it++) {                                          \
            int idx = tid + it * 256;                                             \
            int r = idx >> 3, c4 = idx & 7;                                       \
            cp_async16(&Ad[r * 36 + c4 * 4],                                      \
                       &A[(size_t)(in_base + r) * DIM_ + (k0) + c4 * 4]);         \
        }                                                                         \
        _Pragma("unroll")                                                         \
        for (int it = 0; it < 4; it++) {                                          \
            int idx = tid + it * 256;                                             \
            int r = idx >> 5, c4 = idx & 31;                                      \
            cp_async16(&Bd[r * 132 + c4 * 4],                                     \
                       &W[(size_t)((k0) + r) * DIM_ + n0 + c4 * 4]);              \
        }                                                                         \
    } while (0)

    GEMM_PREFETCH(0, 0);
    asm volatile("cp.async.commit_group;\n");

    int buf = 0;
    for (int t = 0; t < DIM_ / 32; t++) {
        if (t + 1 < DIM_ / 32) GEMM_PREFETCH((t + 1) * 32, buf ^ 1);
        asm volatile("cp.async.commit_group;\n");
        asm volatile("cp.async.wait_group 1;\n");
        __syncthreads();

        float* Ab = As + buf * (128 * 36);
        float* Bb = Bs + buf * (32 * 132);

        #pragma unroll
        for (int kk = 0; kk < 32; kk += 8) {
            wmma::fragment<wmma::matrix_a, 16, 16, 8, wmma::precision::tf32, wmma::row_major> af[4];
            wmma::fragment<wmma::matrix_b, 16, 16, 8, wmma::precision::tf32, wmma::row_major> bf[2];
            #pragma unroll
            for (int i = 0; i < 4; i++) {
                wmma::load_matrix_sync(af[i], &Ab[(wm * 64 + i * 16) * 36 + kk], 36);
                #pragma unroll
                for (int e = 0; e < af[i].num_elements; e++)
                    af[i].x[e] = wmma::__float_to_tf32(af[i].x[e]);
            }
            #pragma unroll
            for (int j = 0; j < 2; j++) {
                wmma::load_matrix_sync(bf[j], &Bb[kk * 132 + wn * 32 + j * 16], 132);
                #pragma unroll
                for (int e = 0; e < bf[j].num_elements; e++)
                    bf[j].x[e] = wmma::__float_to_tf32(bf[j].x[e]);
            }
            #pragma unroll
            for (int i = 0; i < 4; i++)
                #pragma unroll
                for (int j = 0; j < 2; j++)
                    wmma::mma_sync(cf[i][j], af[i], bf[j], cf[i][j]);
        }
        __syncthreads();
        buf ^= 1;
    }

    // Epilogue: stage through smem (reuse buffers), add bias, contiguous store.
    float* Cs = sm;   // 128 x 132 = 16896 floats <= 17664
    #pragma unroll
    for (int i = 0; i < 4; i++)
        #pragma unroll
        for (int j = 0; j < 2; j++)
            wmma::store_matrix_sync(&Cs[(wm * 64 + i * 16) * 132 + wn * 32 + j * 16],
                                    cf[i][j], 132, wmma::mem_row_major);
    __syncthreads();

    #pragma unroll
    for (int it = 0; it < 16; it++) {
        int idx4 = tid + it * 256;      // 0..4095 float4s (128 rows x 32)
        int r = idx4 >> 5, c4 = idx4 & 31;
        float4 v  = *(float4*)&Cs[r * 132 + c4 * 4];
        float4 bb = *(const float4*)&bias[n0 + c4 * 4];
        v.x += bb.x; v.y += bb.y; v.z += bb.z; v.w += bb.w;
        *(float4*)&C[(size_t)(out_base + r) * DIM_ + n0 + c4 * 4] = v;
    }
}

// ---------------------------------------------------------------------------
// Fused RMSNorm + RoPE, in-place on joint Q (z=0) and K (z=1).
// ---------------------------------------------------------------------------
__global__ void __launch_bounds__(128) rms_rope_kernel(
    float* __restrict__ q, float* __restrict__ k,
    const float* __restrict__ cosr, const float* __restrict__ sinr,
    const float* __restrict__ gq, const float* __restrict__ gk,
    const float* __restrict__ gqc, const float* __restrict__ gkc)
{
    const int j = blockIdx.x, b = blockIdx.y, which = blockIdx.z;
    float* buf = which ? k : q;
    const float* g = which ? (j < S_TXT_ ? gkc : gk)
                           : (j < S_TXT_ ? gqc : gq);
    const int lane = threadIdx.x & 31;
    const int warp = threadIdx.x >> 5;
    const size_t rowbase = ((size_t)(b * S_TOT + j)) * DIM_;

    const float c0 = cosr[j * 64 + lane];
    const float s0 = sinr[j * 64 + lane];
    const float c1 = cosr[j * 64 + lane + 32];
    const float s1 = sinr[j * 64 + lane + 32];

    for (int h = warp; h < HEADS_; h += 4) {
        float* p = buf + rowbase + h * HD_;
        float2 e0 = *(float2*)&p[2 * lane];
        float2 e1 = *(float2*)&p[2 * (lane + 32)];
        float ss = e0.x * e0.x + e0.y * e0.y + e1.x * e1.x + e1.y * e1.y;
        #pragma unroll
        for (int o = 16; o; o >>= 1) ss += __shfl_xor_sync(0xffffffffu, ss, o);
        float inv = rsqrtf(ss * (1.0f / 128.0f) + 1e-6f);

        float x1 = e0.x * inv * g[2 * lane];
        float x2 = e0.y * inv * g[2 * lane + 1];
        float y1 = e1.x * inv * g[2 * (lane + 32)];
        float y2 = e1.y * inv * g[2 * (lane + 32) + 1];

        float2 o0 = make_float2(x1 * c0 - x2 * s0, x1 * s0 + x2 * c0);
        float2 o1 = make_float2(y1 * c1 - y2 * s1, y1 * s1 + y2 * c1);
        *(float2*)&p[2 * lane] = o0;
        *(float2*)&p[2 * (lane + 32)] = o1;
    }
}

// ---------------------------------------------------------------------------
// Flash-style attention v2. grid (S_TOT/64, HEADS, BATCH), 256 threads.
// Warp grid 4x2 over the 64x128 score tile (warp tile 16 rows x 64 cols).
// Parallel softmax: 4 threads per q-row, float4 + shfl.
// smem (floats, ld=132 padded): K 16896, V 16896, P 8448, O 8448, stats 128.
// ---------------------------------------------------------------------------
#define ATTN_SMEM_BYTES (50816 * 4)

__global__ void __launch_bounds__(256) attn_kernel(
    const float* __restrict__ qj, const float* __restrict__ kj,
    const float* __restrict__ vj, float* __restrict__ oj)
{
    extern __shared__ float sm[];
    float* Ks   = sm;                 // 128 x 132
    float* Vs   = sm + 16896;         // 128 x 132
    float* Ps   = sm + 33792;         // 64 x 132  (Q staging, then scores/P)
    float* Os   = sm + 42240;         // 64 x 132
    float* mrow = sm + 50688;         // 64
    float* lrow = sm + 50752;         // 64

    const int tid  = threadIdx.x;
    const int warp = tid >> 5;
    const int wm   = warp >> 1;       // 0..3 : 16-row block
    const int wn   = warp & 1;        // 0..1 : 64-col block
    const int q0   = blockIdx.x * 64;
    const int h    = blockIdx.y;
    const int b    = blockIdx.z;
    const size_t hd0 = (size_t)h * HD_;

    // Stage Q tile (pre-scaled by SCALE_) into Ps; init O and stats.
    #pragma unroll
    for (int it = 0; it < 8; it++) {
        int idx4 = tid + it * 256;    // 0..2047 (64 rows x 32 float4)
        int r = idx4 >> 5, c4 = idx4 & 31;
        size_t gaddr = ((size_t)(b * S_TOT + q0 + r)) * DIM_ + hd0 + c4 * 4;
        float4 v = *(const float4*)&qj[gaddr];
        v.x *= SCALE_; v.y *= SCALE_; v.z *= SCALE_; v.w *= SCALE_;
        *(float4*)&Ps[r * 132 + c4 * 4] = v;
        *(float4*)&Os[r * 132 + c4 * 4] = make_float4(0.f, 0.f, 0.f, 0.f);
    }
    if (tid < 64) { mrow[tid] = -1e30f; lrow[tid] = 0.f; }
    __syncthreads();

    // Preload Q fragments (16 d-chunks of 8) for this warp's 16 rows.
    wmma::fragment<wmma::matrix_a, 16, 16, 8, wmma::precision::tf32, wmma::row_major> qf[16];
    #pragma unroll
    for (int t = 0; t < 16; t++) {
        wmma::load_matrix_sync(qf[t], &Ps[(wm * 16) * 132 + t * 8], 132);
        #pragma unroll
        for (int e = 0; e < qf[t].num_elements; e++)
            qf[t].x[e] = wmma::__float_to_tf32(qf[t].x[e]);
    }
    __syncthreads();  // Ps reused for scores

    const int r_sm   = tid >> 2;      // softmax row (0..63)
    const int sub    = tid & 3;       // quarter of the row

    for (int kt = 0; kt < S_TOT; kt += 128) {
        // Load K and V tiles (each 128x128, padded ld 132).
        #pragma unroll
        for (int it = 0; it < 16; it++) {
            int idx4 = tid + it * 256;   // 0..4095
            int r = idx4 >> 5, c4 = idx4 & 31;
            size_t gaddr = ((size_t)(b * S_TOT + kt + r)) * DIM_ + hd0 + c4 * 4;
            *(float4*)&Ks[r * 132 + c4 * 4] = *(const float4*)&kj[gaddr];
            *(float4*)&Vs[r * 132 + c4 * 4] = *(const float4*)&vj[gaddr];
        }
        __syncthreads();

        // Scores: warp computes S[wm*16 : +16, wn*64 : +64].
        #pragma unroll
        for (int n = 0; n < 4; n++) {
            wmma::fragment<wmma::accumulator, 16, 16, 8, float> cfr;
            wmma::fill_fragment(cfr, 0.0f);
            #pragma unroll
            for (int kk = 0; kk < 16; kk++) {
                wmma::fragment<wmma::matrix_b, 16, 16, 8, wmma::precision::tf32, wmma::col_major> bf;
                wmma::load_matrix_sync(bf, &Ks[(wn * 64 + n * 16) * 132 + kk * 8], 132);
                #pragma unroll
                for (int e = 0; e < bf.num_elements; e++)
                    bf.x[e] = wmma::__float_to_tf32(bf.x[e]);
                wmma::mma_sync(cfr, qf[kk], bf, cfr);
            }
            wmma::store_matrix_sync(&Ps[(wm * 16) * 132 + wn * 64 + n * 16],
                                    cfr, 132, wmma::mem_row_major);
        }
        __syncthreads();

        // Online softmax: 4 threads per row, 32 cols each (8 float4).
        {
            float* prow = &Ps[r_sm * 132 + sub * 32];
            float mx = -1e30f;
            float4 vv[8];
            #pragma unroll
            for (int i = 0; i < 8; i++) {
                vv[i] = ((float4*)prow)[i];
                mx = fmaxf(mx, fmaxf(fmaxf(vv[i].x, vv[i].y), fmaxf(vv[i].z, vv[i].w)));
            }
            mx = fmaxf(mx, __shfl_xor_sync(0xffffffffu, mx, 1));
            mx = fmaxf(mx, __shfl_xor_sync(0xffffffffu, mx, 2));
            float mold = mrow[r_sm];
            float newm = fmaxf(mold, mx);
            float f = __expf(mold - newm);
            float sum = 0.f;
            #pragma unroll
            for (int i = 0; i < 8; i++) {
                vv[i].x = __expf(vv[i].x - newm);
                vv[i].y = __expf(vv[i].y - newm);
                vv[i].z = __expf(vv[i].z - newm);
                vv[i].w = __expf(vv[i].w - newm);
                sum += vv[i].x + vv[i].y + vv[i].z + vv[i].w;
                ((float4*)prow)[i] = vv[i];
            }
            sum += __shfl_xor_sync(0xffffffffu, sum, 1);
            sum += __shfl_xor_sync(0xffffffffu, sum, 2);
            if (sub == 0) { lrow[r_sm] = lrow[r_sm] * f + sum; mrow[r_sm] = newm; }
            // Rescale O.
            float* orow = &Os[r_sm * 132 + sub * 32];
            #pragma unroll
            for (int i = 0; i < 8; i++) {
                float4 o = ((float4*)orow)[i];
                o.x *= f; o.y *= f; o.z *= f; o.w *= f;
                ((float4*)orow)[i] = o;
            }
        }
        __syncthreads();

        // PV: O[wm*16 : +16, wn*64 : +64] += P @ V.
        wmma::fragment<wmma::matrix_a, 16, 16, 8, wmma::precision::tf32, wmma::row_major> pf[16];
        #pragma unroll
        for (int kk = 0; kk < 16; kk++) {
            wmma::load_matrix_sync(pf[kk], &Ps[(wm * 16) * 132 + kk * 8], 132);
            #pragma unroll
            for (int e = 0; e < pf[kk].num_elements; e++)
                pf[kk].x[e] = wmma::__float_to_tf32(pf[kk].x[e]);
        }
        #pragma unroll
        for (int n = 0; n < 4; n++) {
            wmma::fragment<wmma::accumulator, 16, 16, 8, float> cfr;
            wmma::load_matrix_sync(cfr, &Os[(wm * 16) * 132 + wn * 64 + n * 16],
                                   132, wmma::mem_row_major);
            #pragma unroll
            for (int kk = 0; kk < 16; kk++) {
                wmma::fragment<wmma::matrix_b, 16, 16, 8, wmma::precision::tf32, wmma::row_major> bf;
                wmma::load_matrix_sync(bf, &Vs[(kk * 8) * 132 + wn * 64 + n * 16], 132);
                #pragma unroll
                for (int e = 0; e < bf.num_elements; e++)
                    bf.x[e] = wmma::__float_to_tf32(bf.x[e]);
                wmma::mma_sync(cfr, pf[kk], bf, cfr);
            }
            wmma::store_matrix_sync(&Os[(wm * 16) * 132 + wn * 64 + n * 16],
                                    cfr, 132, wmma::mem_row_major);
        }
        __syncthreads();
    }

    // Writeout: O / l.
    #pragma unroll
    for (int it = 0; it < 8; it++) {
        int idx4 = tid + it * 256;
        int r = idx4 >> 5, c4 = idx4 & 31;
        float inv = 1.0f / lrow[r];
        float4 v = *(float4*)&Os[r * 132 + c4 * 4];
        v.x *= inv; v.y *= inv; v.z *= inv; v.w *= inv;
        size_t gaddr = ((size_t)(b * S_TOT + q0 + r)) * DIM_ + hd0 + c4 * 4;
        *(float4*)&oj[gaddr] = v;
    }
}

// ---------------------------------------------------------------------------
extern "C" void kernel_launch(void* const* d_in, const int* in_sizes, int n_in,
                              void* d_out, int out_size)
{
    const float* x    = (const float*)d_in[0];
    const float* ctx  = (const float*)d_in[1];
    const float* cosr = (const float*)d_in[2];
    const float* sinr = (const float*)d_in[3];
    const float* wq   = (const float*)d_in[4];
    const float* bq   = (const float*)d_in[5];
    const float* wk   = (const float*)d_in[6];
    const float* bk   = (const float*)d_in[7];
    const float* wv   = (const float*)d_in[8];
    const float* bv   = (const float*)d_in[9];
    const float* wqc  = (const float*)d_in[10];
    const float* bqc  = (const float*)d_in[11];
    const float* wkc  = (const float*)d_in[12];
    const float* bkc  = (const float*)d_in[13];
    const float* wvc  = (const float*)d_in[14];
    const float* bvc  = (const float*)d_in[15];
    const float* w_out     = (const float*)d_in[16];
    const float* b_out     = (const float*)d_in[17];
    const float* w_add_out = (const float*)d_in[18];
    const float* b_add_out = (const float*)d_in[19];
    const float* gq  = (const float*)d_in[20];
    const float* gk  = (const float*)d_in[21];
    const float* gqc = (const float*)d_in[22];
    const float* gkc = (const float*)d_in[23];
    float* out = (float*)d_out;

    float *qj, *kj, *vj, *oj;
    cudaGetSymbolAddress((void**)&qj, g_qj);
    cudaGetSymbolAddress((void**)&kj, g_kj);
    cudaGetSymbolAddress((void**)&vj, g_vj);
    cudaGetSymbolAddress((void**)&oj, g_oj);

    cudaFuncSetAttribute(gemm_tf32, cudaFuncAttributeMaxDynamicSharedMemorySize,
                         GEMM_SMEM_BYTES);
    cudaFuncSetAttribute(attn_kernel, cudaFuncAttributeMaxDynamicSharedMemorySize,
                         ATTN_SMEM_BYTES);

    const dim3 blk(256);
    // QKV projections for x (M=2048) -> joint rows b*1536 + 512 + s
    gemm_tf32<<<dim3(24, 16), blk, GEMM_SMEM_BYTES>>>(x, 2048, 2048, 0, wq, bq, qj, 1024, 1536, 512);
    gemm_tf32<<<dim3(24, 16), blk, GEMM_SMEM_BYTES>>>(x, 2048, 2048, 0, wk, bk, kj, 1024, 1536, 512);
    gemm_tf32<<<dim3(24, 16), blk, GEMM_SMEM_BYTES>>>(x, 2048, 2048, 0, wv, bv, vj, 1024, 1536, 512);
    // QKV projections for ctx (M=1024) -> joint rows b*1536 + s
    gemm_tf32<<<dim3(24, 8), blk, GEMM_SMEM_BYTES>>>(ctx, 1024, 1024, 0, wqc, bqc, qj, 512, 1536, 0);
    gemm_tf32<<<dim3(24, 8), blk, GEMM_SMEM_BYTES>>>(ctx, 1024, 1024, 0, wkc, bkc, kj, 512, 1536, 0);
    gemm_tf32<<<dim3(24, 8), blk, GEMM_SMEM_BYTES>>>(ctx, 1024, 1024, 0, wvc, bvc, vj, 512, 1536, 0);

    // RMS norm + RoPE in-place on joint Q and K
    rms_rope_kernel<<<dim3(S_TOT, BATCH, 2), dim3(128)>>>(qj, kj, cosr, sinr, gq, gk, gqc, gkc);

    // Attention -> oj (joint layout)
    attn_kernel<<<dim3(S_TOT / 64, HEADS_, BATCH), blk, ATTN_SMEM_BYTES>>>(qj, kj, vj, oj);

    // Output projections
    gemm_tf32<<<dim3(24, 8), blk, GEMM_SMEM_BYTES>>>(oj, 512, 1536, 0, w_add_out, b_add_out,
                                                     out, 1024, 1024, 0);
    gemm_tf32<<<dim3(24, 16), blk, GEMM_SMEM_BYTES>>>(oj, 1024, 1536, 512, w_out, b_out,
                                                      out + (size_t)BATCH * S_TXT_ * DIM_, 2048, 2048, 0);
}

// round 6
// speedup vs baseline: 1.8439x; 1.1657x over previous
#include <cstdint>
#include <cuda_runtime.h>
#include <cuda_bf16.h>
#include <mma.h>

using namespace nvcuda;

#define DIM_   3072
#define S_TOT  1536
#define S_TXT_ 512
#define BATCH  2
#define HD_    128
#define HEADS_ 24
#define SCALE_ 0.08838834764831845f   // 1/sqrt(128)
#define QSCALE_ (SCALE_ * 1.4426950408889634f)   // fold log2(e) for exp2 softmax

#define JOINT_ELEMS (BATCH * S_TOT * DIM_)   // 9,437,184
#define W_ELEMS (DIM_ * DIM_)                // 9,437,184

// Scratch (no allocations allowed).
__device__ float g_qj[JOINT_ELEMS];
__device__ float g_kj[JOINT_ELEMS];
__device__ float g_vj[JOINT_ELEMS];
__device__ float g_oj[JOINT_ELEMS];
__device__ float g_wr[8 * W_ELEMS];          // tf32-rounded weights
__device__ float g_xr[BATCH * 1024 * DIM_];  // tf32-rounded x
__device__ float g_cr[BATCH * 512 * DIM_];   // tf32-rounded ctx

__device__ __forceinline__ float tf32r(float x) { return wmma::__float_to_tf32(x); }

__device__ __forceinline__ void cp_async16(void* smem_dst, const void* gmem_src) {
    unsigned int d = (unsigned int)__cvta_generic_to_shared(smem_dst);
    asm volatile("cp.async.cg.shared.global [%0], [%1], 16;\n" :: "r"(d), "l"(gmem_src));
}

// ---------------------------------------------------------------------------
// Pre-pass: round tensors to tf32 (RN) once, so MMA consumers skip conversion.
// ---------------------------------------------------------------------------
struct RoundSrc8 { const float* s[8]; };

__global__ void __launch_bounds__(256) round_w_kernel(RoundSrc8 rs, float* __restrict__ dst) {
    int t = blockIdx.x * 256 + threadIdx.x;            // float4 index
    int w = blockIdx.y;
    float4 v = ((const float4*)rs.s[w])[t];
    v.x = tf32r(v.x); v.y = tf32r(v.y); v.z = tf32r(v.z); v.w = tf32r(v.w);
    ((float4*)dst)[(size_t)w * (W_ELEMS / 4) + t] = v;
}

__global__ void __launch_bounds__(256) round_kernel(const float* __restrict__ src,
                                                    float* __restrict__ dst) {
    int t = blockIdx.x * 256 + threadIdx.x;
    float4 v = ((const float4*)src)[t];
    v.x = tf32r(v.x); v.y = tf32r(v.y); v.z = tf32r(v.z); v.w = tf32r(v.w);
    ((float4*)dst)[t] = v;
}

// ---------------------------------------------------------------------------
// TF32 GEMM v3: BM=128, BN=128, BK=32, 256 threads, cp.async double-buffered.
// All inputs pre-rounded to tf32 -> NO per-fragment conversion.
// Multi-job: blockIdx.z selects job (merged launches for wave packing).
// ---------------------------------------------------------------------------
#define GEMM_SMEM_BYTES (17664 * 4)

struct GemmJob {
    const float* A; const float* W; const float* bias; float* C;
    int in_rpb, in_bsr, in_off;
    int out_rpb, out_bsr, out_off;
    int grid_y, round_out;
};
struct GemmJobs6 { GemmJob j[6]; };

__global__ void __launch_bounds__(256, 2) gemm_tf32(GemmJobs6 jobs)
{
    const GemmJob jb = jobs.j[blockIdx.z];
    if ((int)blockIdx.y >= jb.grid_y) return;

    extern __shared__ float sm[];
    float* As = sm;                 // 2 buffers of 128*36
    float* Bs = sm + 2 * 128 * 36;  // 2 buffers of 32*132

    const float* __restrict__ A = jb.A;
    const float* __restrict__ W = jb.W;

    const int tid  = threadIdx.x;
    const int warp = tid >> 5;
    const int wm   = warp >> 2;     // 0..1 : row block of 64
    const int wn   = warp & 3;      // 0..3 : col block of 32
    const int m0   = blockIdx.y * 128;
    const int n0   = blockIdx.x * 128;
    const int in_base  = (m0 / jb.in_rpb) * jb.in_bsr + jb.in_off + (m0 % jb.in_rpb);
    const int out_base = (m0 / jb.out_rpb) * jb.out_bsr + jb.out_off + (m0 % jb.out_rpb);

    wmma::fragment<wmma::accumulator, 16, 16, 8, float> cf[4][2];
    #pragma unroll
    for (int i = 0; i < 4; i++)
        #pragma unroll
        for (int j = 0; j < 2; j++)
            wmma::fill_fragment(cf[i][j], 0.0f);

    #define GEMM_PREFETCH(k0, bufi) do {                                          \
        float* Ad = As + (bufi) * (128 * 36);                                     \
        float* Bd = Bs + (bufi) * (32 * 132);                                     \
        _Pragma("unroll")                                                         \
        for (int it = 0; it < 4; it++) {                                          \
            int idx = tid + it * 256;                                             \
            int r = idx >> 3, c4 = idx & 7;                                       \
            cp_async16(&Ad[r * 36 + c4 * 4],                                      \
                       &A[(size_t)(in_base + r) * DIM_ + (k0) + c4 * 4]);         \
        }                                                                         \
        _Pragma("unroll")                                                         \
        for (int it = 0; it < 4; it++) {                                          \
            int idx = tid + it * 256;                                             \
            int r = idx >> 5, c4 = idx & 31;                                      \
            cp_async16(&Bd[r * 132 + c4 * 4],                                     \
                       &W[(size_t)((k0) + r) * DIM_ + n0 + c4 * 4]);              \
        }                                                                         \
    } while (0)

    GEMM_PREFETCH(0, 0);
    asm volatile("cp.async.commit_group;\n");

    int buf = 0;
    for (int t = 0; t < DIM_ / 32; t++) {
        if (t + 1 < DIM_ / 32) GEMM_PREFETCH((t + 1) * 32, buf ^ 1);
        asm volatile("cp.async.commit_group;\n");
        asm volatile("cp.async.wait_group 1;\n");
        __syncthreads();

        float* Ab = As + buf * (128 * 36);
        float* Bb = Bs + buf * (32 * 132);

        #pragma unroll
        for (int kk = 0; kk < 32; kk += 8) {
            wmma::fragment<wmma::matrix_a, 16, 16, 8, wmma::precision::tf32, wmma::row_major> af[4];
            wmma::fragment<wmma::matrix_b, 16, 16, 8, wmma::precision::tf32, wmma::row_major> bf[2];
            #pragma unroll
            for (int i = 0; i < 4; i++)
                wmma::load_matrix_sync(af[i], &Ab[(wm * 64 + i * 16) * 36 + kk], 36);
            #pragma unroll
            for (int j = 0; j < 2; j++)
                wmma::load_matrix_sync(bf[j], &Bb[kk * 132 + wn * 32 + j * 16], 132);
            #pragma unroll
            for (int i = 0; i < 4; i++)
                #pragma unroll
                for (int j = 0; j < 2; j++)
                    wmma::mma_sync(cf[i][j], af[i], bf[j], cf[i][j]);
        }
        __syncthreads();
        buf ^= 1;
    }

    // Epilogue: stage through smem, add bias, optional tf32 round, store.
    float* Cs = sm;   // 128 x 132
    #pragma unroll
    for (int i = 0; i < 4; i++)
        #pragma unroll
        for (int j = 0; j < 2; j++)
            wmma::store_matrix_sync(&Cs[(wm * 64 + i * 16) * 132 + wn * 32 + j * 16],
                                    cf[i][j], 132, wmma::mem_row_major);
    __syncthreads();

    #pragma unroll
    for (int it = 0; it < 16; it++) {
        int idx4 = tid + it * 256;
        int r = idx4 >> 5, c4 = idx4 & 31;
        float4 v  = *(float4*)&Cs[r * 132 + c4 * 4];
        float4 bb = *(const float4*)&jb.bias[n0 + c4 * 4];
        v.x += bb.x; v.y += bb.y; v.z += bb.z; v.w += bb.w;
        if (jb.round_out) {
            v.x = tf32r(v.x); v.y = tf32r(v.y); v.z = tf32r(v.z); v.w = tf32r(v.w);
        }
        *(float4*)&jb.C[(size_t)(out_base + r) * DIM_ + n0 + c4 * 4] = v;
    }
}

// ---------------------------------------------------------------------------
// Fused RMSNorm + RoPE, in-place on joint Q (z=0) and K (z=1). Rounds outputs
// to tf32 so attention fragment loads need no conversion.
// ---------------------------------------------------------------------------
__global__ void __launch_bounds__(128) rms_rope_kernel(
    float* __restrict__ q, float* __restrict__ k,
    const float* __restrict__ cosr, const float* __restrict__ sinr,
    const float* __restrict__ gq, const float* __restrict__ gk,
    const float* __restrict__ gqc, const float* __restrict__ gkc)
{
    const int j = blockIdx.x, b = blockIdx.y, which = blockIdx.z;
    float* buf = which ? k : q;
    const float* g = which ? (j < S_TXT_ ? gkc : gk)
                           : (j < S_TXT_ ? gqc : gq);
    const int lane = threadIdx.x & 31;
    const int warp = threadIdx.x >> 5;
    const size_t rowbase = ((size_t)(b * S_TOT + j)) * DIM_;

    const float c0 = cosr[j * 64 + lane];
    const float s0 = sinr[j * 64 + lane];
    const float c1 = cosr[j * 64 + lane + 32];
    const float s1 = sinr[j * 64 + lane + 32];

    for (int h = warp; h < HEADS_; h += 4) {
        float* p = buf + rowbase + h * HD_;
        float2 e0 = *(float2*)&p[2 * lane];
        float2 e1 = *(float2*)&p[2 * (lane + 32)];
        float ss = e0.x * e0.x + e0.y * e0.y + e1.x * e1.x + e1.y * e1.y;
        #pragma unroll
        for (int o = 16; o; o >>= 1) ss += __shfl_xor_sync(0xffffffffu, ss, o);
        float inv = rsqrtf(ss * (1.0f / 128.0f) + 1e-6f);

        float x1 = e0.x * inv * g[2 * lane];
        float x2 = e0.y * inv * g[2 * lane + 1];
        float y1 = e1.x * inv * g[2 * (lane + 32)];
        float y2 = e1.y * inv * g[2 * (lane + 32) + 1];

        float2 o0 = make_float2(tf32r(x1 * c0 - x2 * s0), tf32r(x1 * s0 + x2 * c0));
        float2 o1 = make_float2(tf32r(y1 * c1 - y2 * s1), tf32r(y1 * s1 + y2 * c1));
        *(float2*)&p[2 * lane] = o0;
        *(float2*)&p[2 * (lane + 32)] = o1;
    }
}

// ---------------------------------------------------------------------------
// Flash-style attention v3. grid (S_TOT/64, HEADS, BATCH), 256 threads.
// All MMA operands pre-rounded tf32 -> no conversions in inner loops.
// Softmax in log2 domain (Q pre-scaled by SCALE*log2e), exp2f only.
// ---------------------------------------------------------------------------
#define ATTN_SMEM_BYTES (50816 * 4)

__global__ void __launch_bounds__(256) attn_kernel(
    const float* __restrict__ qj, const float* __restrict__ kj,
    const float* __restrict__ vj, float* __restrict__ oj)
{
    extern __shared__ float sm[];
    float* Ks   = sm;                 // 128 x 132
    float* Vs   = sm + 16896;         // 128 x 132
    float* Ps   = sm + 33792;         // 64 x 132  (Q staging, then scores/P)
    float* Os   = sm + 42240;         // 64 x 132
    float* mrow = sm + 50688;         // 64
    float* lrow = sm + 50752;         // 64

    const int tid  = threadIdx.x;
    const int warp = tid >> 5;
    const int wm   = warp >> 1;       // 0..3 : 16-row block
    const int wn   = warp & 1;        // 0..1 : 64-col block
    const int q0   = blockIdx.x * 64;
    const int h    = blockIdx.y;
    const int b    = blockIdx.z;
    const size_t hd0 = (size_t)h * HD_;

    // Stage Q tile (scaled by SCALE*log2e, re-rounded) into Ps; init O, stats.
    #pragma unroll
    for (int it = 0; it < 8; it++) {
        int idx4 = tid + it * 256;
        int r = idx4 >> 5, c4 = idx4 & 31;
        size_t gaddr = ((size_t)(b * S_TOT + q0 + r)) * DIM_ + hd0 + c4 * 4;
        float4 v = *(const float4*)&qj[gaddr];
        v.x = tf32r(v.x * QSCALE_); v.y = tf32r(v.y * QSCALE_);
        v.z = tf32r(v.z * QSCALE_); v.w = tf32r(v.w * QSCALE_);
        *(float4*)&Ps[r * 132 + c4 * 4] = v;
        *(float4*)&Os[r * 132 + c4 * 4] = make_float4(0.f, 0.f, 0.f, 0.f);
    }
    if (tid < 64) { mrow[tid] = -1e30f; lrow[tid] = 0.f; }
    __syncthreads();

    // Preload Q fragments for this warp's 16 rows (already tf32).
    wmma::fragment<wmma::matrix_a, 16, 16, 8, wmma::precision::tf32, wmma::row_major> qf[16];
    #pragma unroll
    for (int t = 0; t < 16; t++)
        wmma::load_matrix_sync(qf[t], &Ps[(wm * 16) * 132 + t * 8], 132);
    __syncthreads();  // Ps reused for scores

    const int r_sm = tid >> 2;        // softmax row (0..63)
    const int sub  = tid & 3;         // quarter of the row

    for (int kt = 0; kt < S_TOT; kt += 128) {
        // Load K and V tiles via cp.async (values already tf32-rounded).
        #pragma unroll
        for (int it = 0; it < 16; it++) {
            int idx4 = tid + it * 256;
            int r = idx4 >> 5, c4 = idx4 & 31;
            size_t gaddr = ((size_t)(b * S_TOT + kt + r)) * DIM_ + hd0 + c4 * 4;
            cp_async16(&Ks[r * 132 + c4 * 4], &kj[gaddr]);
            cp_async16(&Vs[r * 132 + c4 * 4], &vj[gaddr]);
        }
        asm volatile("cp.async.commit_group;\n");
        asm volatile("cp.async.wait_group 0;\n");
        __syncthreads();

        // Scores: warp computes S[wm*16 : +16, wn*64 : +64] (log2 units).
        #pragma unroll
        for (int n = 0; n < 4; n++) {
            wmma::fragment<wmma::accumulator, 16, 16, 8, float> cfr;
            wmma::fill_fragment(cfr, 0.0f);
            #pragma unroll
            for (int kk = 0; kk < 16; kk++) {
                wmma::fragment<wmma::matrix_b, 16, 16, 8, wmma::precision::tf32, wmma::col_major> bf;
                wmma::load_matrix_sync(bf, &Ks[(wn * 64 + n * 16) * 132 + kk * 8], 132);
                wmma::mma_sync(cfr, qf[kk], bf, cfr);
            }
            wmma::store_matrix_sync(&Ps[(wm * 16) * 132 + wn * 64 + n * 16],
                                    cfr, 132, wmma::mem_row_major);
        }
        __syncthreads();

        // Online softmax (log2 domain): 4 threads per row, 32 cols each.
        {
            float* prow = &Ps[r_sm * 132 + sub * 32];
            float mx = -1e30f;
            float4 vv[8];
            #pragma unroll
            for (int i = 0; i < 8; i++) {
                vv[i] = ((float4*)prow)[i];
                mx = fmaxf(mx, fmaxf(fmaxf(vv[i].x, vv[i].y), fmaxf(vv[i].z, vv[i].w)));
            }
            mx = fmaxf(mx, __shfl_xor_sync(0xffffffffu, mx, 1));
            mx = fmaxf(mx, __shfl_xor_sync(0xffffffffu, mx, 2));
            float mold = mrow[r_sm];
            float newm = fmaxf(mold, mx);
            float f = exp2f(mold - newm);
            float sum = 0.f;
            #pragma unroll
            for (int i = 0; i < 8; i++) {
                vv[i].x = exp2f(vv[i].x - newm);
                vv[i].y = exp2f(vv[i].y - newm);
                vv[i].z = exp2f(vv[i].z - newm);
                vv[i].w = exp2f(vv[i].w - newm);
                sum += vv[i].x + vv[i].y + vv[i].z + vv[i].w;
                vv[i].x = tf32r(vv[i].x); vv[i].y = tf32r(vv[i].y);
                vv[i].z = tf32r(vv[i].z); vv[i].w = tf32r(vv[i].w);
                ((float4*)prow)[i] = vv[i];
            }
            sum += __shfl_xor_sync(0xffffffffu, sum, 1);
            sum += __shfl_xor_sync(0xffffffffu, sum, 2);
            if (sub == 0) { lrow[r_sm] = lrow[r_sm] * f + sum; mrow[r_sm] = newm; }
            // Rescale O.
            float* orow = &Os[r_sm * 132 + sub * 32];
            #pragma unroll
            for (int i = 0; i < 8; i++) {
                float4 o = ((float4*)orow)[i];
                o.x *= f; o.y *= f; o.z *= f; o.w *= f;
                ((float4*)orow)[i] = o;
            }
        }
        __syncthreads();

        // PV: O[wm*16 : +16, wn*64 : +64] += P @ V.
        wmma::fragment<wmma::matrix_a, 16, 16, 8, wmma::precision::tf32, wmma::row_major> pf[16];
        #pragma unroll
        for (int kk = 0; kk < 16; kk++)
            wmma::load_matrix_sync(pf[kk], &Ps[(wm * 16) * 132 + kk * 8], 132);
        #pragma unroll
        for (int n = 0; n < 4; n++) {
            wmma::fragment<wmma::accumulator, 16, 16, 8, float> cfr;
            wmma::load_matrix_sync(cfr, &Os[(wm * 16) * 132 + wn * 64 + n * 16],
                                   132, wmma::mem_row_major);
            #pragma unroll
            for (int kk = 0; kk < 16; kk++) {
                wmma::fragment<wmma::matrix_b, 16, 16, 8, wmma::precision::tf32, wmma::row_major> bf;
                wmma::load_matrix_sync(bf, &Vs[(kk * 8) * 132 + wn * 64 + n * 16], 132);
                wmma::mma_sync(cfr, pf[kk], bf, cfr);
            }
            wmma::store_matrix_sync(&Os[(wm * 16) * 132 + wn * 64 + n * 16],
                                    cfr, 132, wmma::mem_row_major);
        }
        __syncthreads();
    }

    // Writeout: O / l, rounded to tf32 (feeds the output-projection GEMMs).
    #pragma unroll
    for (int it = 0; it < 8; it++) {
        int idx4 = tid + it * 256;
        int r = idx4 >> 5, c4 = idx4 & 31;
        float inv = 1.0f / lrow[r];
        float4 v = *(float4*)&Os[r * 132 + c4 * 4];
        v.x = tf32r(v.x * inv); v.y = tf32r(v.y * inv);
        v.z = tf32r(v.z * inv); v.w = tf32r(v.w * inv);
        size_t gaddr = ((size_t)(b * S_TOT + q0 + r)) * DIM_ + hd0 + c4 * 4;
        *(float4*)&oj[gaddr] = v;
    }
}

// ---------------------------------------------------------------------------
extern "C" void kernel_launch(void* const* d_in, const int* in_sizes, int n_in,
                              void* d_out, int out_size)
{
    const float* x    = (const float*)d_in[0];
    const float* ctx  = (const float*)d_in[1];
    const float* cosr = (const float*)d_in[2];
    const float* sinr = (const float*)d_in[3];
    const float* wq   = (const float*)d_in[4];
    const float* bq   = (const float*)d_in[5];
    const float* wk   = (const float*)d_in[6];
    const float* bk   = (const float*)d_in[7];
    const float* wv   = (const float*)d_in[8];
    const float* bv   = (const float*)d_in[9];
    const float* wqc  = (const float*)d_in[10];
    const float* bqc  = (const float*)d_in[11];
    const float* wkc  = (const float*)d_in[12];
    const float* bkc  = (const float*)d_in[13];
    const float* wvc  = (const float*)d_in[14];
    const float* bvc  = (const float*)d_in[15];
    const float* w_out     = (const float*)d_in[16];
    const float* b_out     = (const float*)d_in[17];
    const float* w_add_out = (const float*)d_in[18];
    const float* b_add_out = (const float*)d_in[19];
    const float* gq  = (const float*)d_in[20];
    const float* gk  = (const float*)d_in[21];
    const float* gqc = (const float*)d_in[22];
    const float* gkc = (const float*)d_in[23];
    float* out = (float*)d_out;

    float *qj, *kj, *vj, *oj, *wr, *xr, *cr;
    cudaGetSymbolAddress((void**)&qj, g_qj);
    cudaGetSymbolAddress((void**)&kj, g_kj);
    cudaGetSymbolAddress((void**)&vj, g_vj);
    cudaGetSymbolAddress((void**)&oj, g_oj);
    cudaGetSymbolAddress((void**)&wr, g_wr);
    cudaGetSymbolAddress((void**)&xr, g_xr);
    cudaGetSymbolAddress((void**)&cr, g_cr);

    cudaFuncSetAttribute(gemm_tf32, cudaFuncAttributeMaxDynamicSharedMemorySize,
                         GEMM_SMEM_BYTES);
    cudaFuncSetAttribute(attn_kernel, cudaFuncAttributeMaxDynamicSharedMemorySize,
                         ATTN_SMEM_BYTES);

    // --- Pre-pass: round weights + activations to tf32 ---
    RoundSrc8 rs;
    rs.s[0] = wq;  rs.s[1] = wk;  rs.s[2] = wv;
    rs.s[3] = wqc; rs.s[4] = wkc; rs.s[5] = wvc;
    rs.s[6] = w_out; rs.s[7] = w_add_out;
    round_w_kernel<<<dim3(W_ELEMS / 4 / 256, 8), 256>>>(rs, wr);
    round_kernel<<<BATCH * 1024 * DIM_ / 4 / 256, 256>>>(x, xr);
    round_kernel<<<BATCH * 512 * DIM_ / 4 / 256, 256>>>(ctx, cr);

    // --- Merged QKV GEMMs (6 jobs in one launch) ---
    GemmJobs6 qkv;
    // x-stream (M=2048): out rows b*1536 + 512 + s
    qkv.j[0] = { xr, wr + 0 * (size_t)W_ELEMS, bq, qj, 2048, 2048, 0, 1024, 1536, 512, 16, 0 };
    qkv.j[1] = { xr, wr + 1 * (size_t)W_ELEMS, bk, kj, 2048, 2048, 0, 1024, 1536, 512, 16, 0 };
    qkv.j[2] = { xr, wr + 2 * (size_t)W_ELEMS, bv, vj, 2048, 2048, 0, 1024, 1536, 512, 16, 1 };
    // ctx-stream (M=1024): out rows b*1536 + s
    qkv.j[3] = { cr, wr + 3 * (size_t)W_ELEMS, bqc, qj, 1024, 1024, 0, 512, 1536, 0, 8, 0 };
    qkv.j[4] = { cr, wr + 4 * (size_t)W_ELEMS, bkc, kj, 1024, 1024, 0, 512, 1536, 0, 8, 0 };
    qkv.j[5] = { cr, wr + 5 * (size_t)W_ELEMS, bvc, vj, 1024, 1024, 0, 512, 1536, 0, 8, 1 };
    gemm_tf32<<<dim3(24, 16, 6), 256, GEMM_SMEM_BYTES>>>(qkv);

    // --- RMS norm + RoPE (rounds q/k to tf32) ---
    rms_rope_kernel<<<dim3(S_TOT, BATCH, 2), dim3(128)>>>(qj, kj, cosr, sinr, gq, gk, gqc, gkc);

    // --- Attention ---
    attn_kernel<<<dim3(S_TOT / 64, HEADS_, BATCH), 256, ATTN_SMEM_BYTES>>>(qj, kj, vj, oj);

    // --- Merged output projections (2 jobs) ---
    GemmJobs6 outp;
    outp.j[0] = { oj, wr + 7 * (size_t)W_ELEMS, b_add_out, out,
                  512, 1536, 0, 1024, 1024, 0, 8, 0 };   // txt
    outp.j[1] = { oj, wr + 6 * (size_t)W_ELEMS, b_out, out + (size_t)BATCH * S_TXT_ * DIM_,
                  1024, 1536, 512, 2048, 2048, 0, 16, 0 }; // img
    outp.j[2] = outp.j[0]; outp.j[3] = outp.j[0]; outp.j[4] = outp.j[0]; outp.j[5] = outp.j[0];
    gemm_tf32<<<dim3(24, 16, 2), 256, GEMM_SMEM_BYTES>>>(outp);
}

// round 11
// speedup vs baseline: 1.9562x; 1.0609x over previous
#include <cstdint>
#include <cuda_runtime.h>
#include <cuda_bf16.h>
#include <mma.h>

using namespace nvcuda;

#define DIM_   3072
#define S_TOT  1536
#define S_TXT_ 512
#define BATCH  2
#define HD_    128
#define HEADS_ 24
#define SCALE_ 0.08838834764831845f   // 1/sqrt(128)
#define QSCALE_ (SCALE_ * 1.4426950408889634f)   // fold log2(e) for exp2 softmax

#define JOINT_ELEMS (BATCH * S_TOT * DIM_)   // 9,437,184
#define W_ELEMS (DIM_ * DIM_)                // 9,437,184

// Scratch (no allocations allowed).
__device__ float g_qj[JOINT_ELEMS];
__device__ float g_kj[JOINT_ELEMS];
__device__ float g_vj[JOINT_ELEMS];
__device__ float g_oj[JOINT_ELEMS];
__device__ float g_wr[8 * W_ELEMS];          // tf32-rounded weights [K,N]
__device__ float g_xr[BATCH * 1024 * DIM_];  // tf32-rounded x
__device__ float g_cr[BATCH * 512 * DIM_];   // tf32-rounded ctx

__device__ __forceinline__ float tf32r(float x) { return wmma::__float_to_tf32(x); }

__device__ __forceinline__ void cp_async16(void* smem_dst, const void* gmem_src) {
    unsigned int d = (unsigned int)__cvta_generic_to_shared(smem_dst);
    asm volatile("cp.async.cg.shared.global [%0], [%1], 16;\n" :: "r"(d), "l"(gmem_src));
}
#define CP_COMMIT() asm volatile("cp.async.commit_group;\n")
#define CP_WAIT(n)  asm volatile("cp.async.wait_group %0;\n" :: "n"(n))

// ---------------------------------------------------------------------------
// Pre-pass: round tensors to tf32 (RN) once, so MMA consumers skip conversion.
// ---------------------------------------------------------------------------
struct RoundSrc8 { const float* s[8]; };

__global__ void __launch_bounds__(256) round_w_kernel(RoundSrc8 rs, float* __restrict__ dst) {
    int t = blockIdx.x * 256 + threadIdx.x;            // float4 index
    int w = blockIdx.y;
    float4 v = ((const float4*)rs.s[w])[t];
    v.x = tf32r(v.x); v.y = tf32r(v.y); v.z = tf32r(v.z); v.w = tf32r(v.w);
    ((float4*)dst)[(size_t)w * (W_ELEMS / 4) + t] = v;
}

__global__ void __launch_bounds__(256) round_kernel(const float* __restrict__ src,
                                                    float* __restrict__ dst) {
    int t = blockIdx.x * 256 + threadIdx.x;
    float4 v = ((const float4*)src)[t];
    v.x = tf32r(v.x); v.y = tf32r(v.y); v.z = tf32r(v.z); v.w = tf32r(v.w);
    ((float4*)dst)[t] = v;
}

// ---------------------------------------------------------------------------
// TF32 GEMM v4: BM=128, BN=256, BK=32, 256 threads (8 warps, 2x4 warp grid,
// warp tile 64x64 -> 8 fragment loads per 16 MMAs). cp.async double-buffered.
// Loop smem: As 2*128*36 + Bs 2*32*260 = 25856 floats.
// Epilogue smem: Cs 128*260 = 33280 floats (allocation size).
// ---------------------------------------------------------------------------
#define GEMM_SMEM_BYTES (33280 * 4)

struct GemmJob {
    const float* A; const float* W; const float* bias; float* C;
    int in_rpb, in_bsr, in_off;
    int out_rpb, out_bsr, out_off;
    int grid_y, round_out;
};
struct GemmJobs6 { GemmJob j[6]; };

__global__ void __launch_bounds__(256) gemm_tf32(GemmJobs6 jobs)
{
    const GemmJob jb = jobs.j[blockIdx.z];
    if ((int)blockIdx.y >= jb.grid_y) return;

    extern __shared__ float sm[];
    float* As = sm;                 // 2 buffers of 128*36
    float* Bs = sm + 2 * 128 * 36;  // 2 buffers of 32*260

    const float* __restrict__ A = jb.A;
    const float* __restrict__ W = jb.W;

    const int tid  = threadIdx.x;
    const int warp = tid >> 5;
    const int wm   = warp >> 2;     // 0..1 : row block of 64
    const int wn   = warp & 3;      // 0..3 : col block of 64
    const int m0   = blockIdx.y * 128;
    const int n0   = blockIdx.x * 256;
    const int in_base  = (m0 / jb.in_rpb) * jb.in_bsr + jb.in_off + (m0 % jb.in_rpb);
    const int out_base = (m0 / jb.out_rpb) * jb.out_bsr + jb.out_off + (m0 % jb.out_rpb);

    wmma::fragment<wmma::accumulator, 16, 16, 8, float> cf[4][4];
    #pragma unroll
    for (int i = 0; i < 4; i++)
        #pragma unroll
        for (int j = 0; j < 4; j++)
            wmma::fill_fragment(cf[i][j], 0.0f);

    // ---- prefetch of one BK=32 tile into buffer bufi ----
    #define GEMM_PREFETCH(k0, bufi) do {                                          \
        float* Ad = As + (bufi) * (128 * 36);                                     \
        float* Bd = Bs + (bufi) * (32 * 260);                                     \
        _Pragma("unroll")                                                         \
        for (int it = 0; it < 4; it++) {                                          \
            int idx = tid + it * 256;                                             \
            int r = idx >> 3, c4 = idx & 7;                                       \
            cp_async16(&Ad[r * 36 + c4 * 4],                                      \
                       &A[(size_t)(in_base + r) * DIM_ + (k0) + c4 * 4]);         \
        }                                                                         \
        _Pragma("unroll")                                                         \
        for (int it = 0; it < 8; it++) {                                          \
            int idx = tid + it * 256;                                             \
            int r = idx >> 6, c4 = idx & 63;                                      \
            cp_async16(&Bd[r * 260 + c4 * 4],                                     \
                       &W[(size_t)((k0) + r) * DIM_ + n0 + c4 * 4]);              \
        }                                                                         \
    } while (0)

    GEMM_PREFETCH(0, 0);
    CP_COMMIT();

    int buf = 0;
    for (int t = 0; t < DIM_ / 32; t++) {
        if (t + 1 < DIM_ / 32) GEMM_PREFETCH((t + 1) * 32, buf ^ 1);
        CP_COMMIT();
        CP_WAIT(1);
        __syncthreads();

        float* Ab = As + buf * (128 * 36);
        float* Bb = Bs + buf * (32 * 260);

        #pragma unroll
        for (int kk = 0; kk < 32; kk += 8) {
            wmma::fragment<wmma::matrix_a, 16, 16, 8, wmma::precision::tf32, wmma::row_major> af[4];
            wmma::fragment<wmma::matrix_b, 16, 16, 8, wmma::precision::tf32, wmma::row_major> bf[4];
            #pragma unroll
            for (int i = 0; i < 4; i++)
                wmma::load_matrix_sync(af[i], &Ab[(wm * 64 + i * 16) * 36 + kk], 36);
            #pragma unroll
            for (int j = 0; j < 4; j++)
                wmma::load_matrix_sync(bf[j], &Bb[kk * 260 + wn * 64 + j * 16], 260);
            #pragma unroll
            for (int i = 0; i < 4; i++)
                #pragma unroll
                for (int j = 0; j < 4; j++)
                    wmma::mma_sync(cf[i][j], af[i], bf[j], cf[i][j]);
        }
        __syncthreads();
        buf ^= 1;
    }

    // Epilogue: stage through smem, add bias, optional tf32 round, store.
    float* Cs = sm;   // 128 x 260
    #pragma unroll
    for (int i = 0; i < 4; i++)
        #pragma unroll
        for (int j = 0; j < 4; j++)
            wmma::store_matrix_sync(&Cs[(wm * 64 + i * 16) * 260 + wn * 64 + j * 16],
                                    cf[i][j], 260, wmma::mem_row_major);
    __syncthreads();

    #pragma unroll
    for (int it = 0; it < 32; it++) {
        int idx4 = tid + it * 256;      // 0..8191 float4s (128 rows x 64)
        int r = idx4 >> 6, c4 = idx4 & 63;
        float4 v  = *(float4*)&Cs[r * 260 + c4 * 4];
        float4 bb = *(const float4*)&jb.bias[n0 + c4 * 4];
        v.x += bb.x; v.y += bb.y; v.z += bb.z; v.w += bb.w;
        if (jb.round_out) {
            v.x = tf32r(v.x); v.y = tf32r(v.y); v.z = tf32r(v.z); v.w = tf32r(v.w);
        }
        *(float4*)&jb.C[(size_t)(out_base + r) * DIM_ + n0 + c4 * 4] = v;
    }
}

// ---------------------------------------------------------------------------
// Fused RMSNorm + RoPE, in-place on joint Q (z=0) and K (z=1). Rounds outputs
// to tf32 so attention fragment loads need no conversion.
// ---------------------------------------------------------------------------
__global__ void __launch_bounds__(128) rms_rope_kernel(
    float* __restrict__ q, float* __restrict__ k,
    const float* __restrict__ cosr, const float* __restrict__ sinr,
    const float* __restrict__ gq, const float* __restrict__ gk,
    const float* __restrict__ gqc, const float* __restrict__ gkc)
{
    const int j = blockIdx.x, b = blockIdx.y, which = blockIdx.z;
    float* buf = which ? k : q;
    const float* g = which ? (j < S_TXT_ ? gkc : gk)
                           : (j < S_TXT_ ? gqc : gq);
    const int lane = threadIdx.x & 31;
    const int warp = threadIdx.x >> 5;
    const size_t rowbase = ((size_t)(b * S_TOT + j)) * DIM_;

    const float c0 = cosr[j * 64 + lane];
    const float s0 = sinr[j * 64 + lane];
    const float c1 = cosr[j * 64 + lane + 32];
    const float s1 = sinr[j * 64 + lane + 32];

    for (int h = warp; h < HEADS_; h += 4) {
        float* p = buf + rowbase + h * HD_;
        float2 e0 = *(float2*)&p[2 * lane];
        float2 e1 = *(float2*)&p[2 * (lane + 32)];
        float ss = e0.x * e0.x + e0.y * e0.y + e1.x * e1.x + e1.y * e1.y;
        #pragma unroll
        for (int o = 16; o; o >>= 1) ss += __shfl_xor_sync(0xffffffffu, ss, o);
        float inv = rsqrtf(ss * (1.0f / 128.0f) + 1e-6f);

        float x1 = e0.x * inv * g[2 * lane];
        float x2 = e0.y * inv * g[2 * lane + 1];
        float y1 = e1.x * inv * g[2 * (lane + 32)];
        float y2 = e1.y * inv * g[2 * (lane + 32) + 1];

        float2 o0 = make_float2(tf32r(x1 * c0 - x2 * s0), tf32r(x1 * s0 + x2 * c0));
        float2 o1 = make_float2(tf32r(y1 * c1 - y2 * s1), tf32r(y1 * s1 + y2 * c1));
        *(float2*)&p[2 * lane] = o0;
        *(float2*)&p[2 * (lane + 32)] = o1;
    }
}

// ---------------------------------------------------------------------------
// Flash-style attention v4 (fixed): split K/V cp.async waits + cross-tile
// prefetch. Each load macro covers the FULL 128x128 tile: 16 iters x 256
// threads x 16B = 64KB = 128 rows x 32 float4.  (R9 bug: it<8 loaded only
// rows 0..63.)
// ---------------------------------------------------------------------------
#define ATTN_SMEM_BYTES (50816 * 4)

__global__ void __launch_bounds__(256) attn_kernel(
    const float* __restrict__ qj, const float* __restrict__ kj,
    const float* __restrict__ vj, float* __restrict__ oj)
{
    extern __shared__ float sm[];
    float* Ks   = sm;                 // 128 x 132
    float* Vs   = sm + 16896;         // 128 x 132
    float* Ps   = sm + 33792;         // 64 x 132
    float* Os   = sm + 42240;         // 64 x 132
    float* mrow = sm + 50688;         // 64
    float* lrow = sm + 50752;         // 64

    const int tid  = threadIdx.x;
    const int warp = tid >> 5;
    const int wm   = warp >> 1;
    const int wn   = warp & 1;
    const int q0   = blockIdx.x * 64;
    const int h    = blockIdx.y;
    const int b    = blockIdx.z;
    const size_t hd0 = (size_t)h * HD_;

    #define ATTN_LOAD_K(kt) do {                                                  \
        _Pragma("unroll")                                                         \
        for (int it = 0; it < 16; it++) {                                         \
            int idx4 = tid + it * 256;                                            \
            int r = idx4 >> 5, c4 = idx4 & 31;                                    \
            size_t gaddr = ((size_t)(b * S_TOT + (kt) + r)) * DIM_ + hd0 + c4 * 4;\
            cp_async16(&Ks[r * 132 + c4 * 4], &kj[gaddr]);                        \
        }                                                                         \
    } while (0)
    #define ATTN_LOAD_V(kt) do {                                                  \
        _Pragma("unroll")                                                         \
        for (int it = 0; it < 16; it++) {                                         \
            int idx4 = tid + it * 256;                                            \
            int r = idx4 >> 5, c4 = idx4 & 31;                                    \
            size_t gaddr = ((size_t)(b * S_TOT + (kt) + r)) * DIM_ + hd0 + c4 * 4;\
            cp_async16(&Vs[r * 132 + c4 * 4], &vj[gaddr]);                        \
        }                                                                         \
    } while (0)

    // Prologue: start K0 / V0 transfers, then stage Q while they fly.
    ATTN_LOAD_K(0); CP_COMMIT();
    ATTN_LOAD_V(0); CP_COMMIT();

    #pragma unroll
    for (int it = 0; it < 8; it++) {
        int idx4 = tid + it * 256;
        int r = idx4 >> 5, c4 = idx4 & 31;
        size_t gaddr = ((size_t)(b * S_TOT + q0 + r)) * DIM_ + hd0 + c4 * 4;
        float4 v = *(const float4*)&qj[gaddr];
        v.x = tf32r(v.x * QSCALE_); v.y = tf32r(v.y * QSCALE_);
        v.z = tf32r(v.z * QSCALE_); v.w = tf32r(v.w * QSCALE_);
        *(float4*)&Ps[r * 132 + c4 * 4] = v;
        *(float4*)&Os[r * 132 + c4 * 4] = make_float4(0.f, 0.f, 0.f, 0.f);
    }
    if (tid < 64) { mrow[tid] = -1e30f; lrow[tid] = 0.f; }
    __syncthreads();

    wmma::fragment<wmma::matrix_a, 16, 16, 8, wmma::precision::tf32, wmma::row_major> qf[16];
    #pragma unroll
    for (int t = 0; t < 16; t++)
        wmma::load_matrix_sync(qf[t], &Ps[(wm * 16) * 132 + t * 8], 132);
    __syncthreads();

    const int r_sm = tid >> 2;
    const int sub  = tid & 3;

    for (int kt = 0; kt < S_TOT; kt += 128) {
        const bool have_next = (kt + 128 < S_TOT);

        // K_i ready (V_i may still be in flight).
        CP_WAIT(1);
        __syncthreads();

        // Scores from Ks.
        #pragma unroll
        for (int n = 0; n < 4; n++) {
            wmma::fragment<wmma::accumulator, 16, 16, 8, float> cfr;
            wmma::fill_fragment(cfr, 0.0f);
            #pragma unroll
            for (int kk = 0; kk < 16; kk++) {
                wmma::fragment<wmma::matrix_b, 16, 16, 8, wmma::precision::tf32, wmma::col_major> bf;
                wmma::load_matrix_sync(bf, &Ks[(wn * 64 + n * 16) * 132 + kk * 8], 132);
                wmma::mma_sync(cfr, qf[kk], bf, cfr);
            }
            wmma::store_matrix_sync(&Ps[(wm * 16) * 132 + wn * 64 + n * 16],
                                    cfr, 132, wmma::mem_row_major);
        }
        __syncthreads();     // Ks fully consumed

        // Prefetch next K into Ks while softmax runs.
        if (have_next) { ATTN_LOAD_K(kt + 128); CP_COMMIT(); }

        // Online softmax (log2 domain).
        {
            float* prow = &Ps[r_sm * 132 + sub * 32];
            float mx = -1e30f;
            float4 vv[8];
            #pragma unroll
            for (int i = 0; i < 8; i++) {
                vv[i] = ((float4*)prow)[i];
                mx = fmaxf(mx, fmaxf(fmaxf(vv[i].x, vv[i].y), fmaxf(vv[i].z, vv[i].w)));
            }
            mx = fmaxf(mx, __shfl_xor_sync(0xffffffffu, mx, 1));
            mx = fmaxf(mx, __shfl_xor_sync(0xffffffffu, mx, 2));
            float mold = mrow[r_sm];
            float newm = fmaxf(mold, mx);
            float f = exp2f(mold - newm);
            float sum = 0.f;
            #pragma unroll
            for (int i = 0; i < 8; i++) {
                vv[i].x = exp2f(vv[i].x - newm);
                vv[i].y = exp2f(vv[i].y - newm);
                vv[i].z = exp2f(vv[i].z - newm);
                vv[i].w = exp2f(vv[i].w - newm);
                sum += vv[i].x + vv[i].y + vv[i].z + vv[i].w;
                vv[i].x = tf32r(vv[i].x); vv[i].y = tf32r(vv[i].y);
                vv[i].z = tf32r(vv[i].z); vv[i].w = tf32r(vv[i].w);
                ((float4*)prow)[i] = vv[i];
            }
            sum += __shfl_xor_sync(0xffffffffu, sum, 1);
            sum += __shfl_xor_sync(0xffffffffu, sum, 2);
            if (sub == 0) { lrow[r_sm] = lrow[r_sm] * f + sum; mrow[r_sm] = newm; }
            float* orow = &Os[r_sm * 132 + sub * 32];
            #pragma unroll
            for (int i = 0; i < 8; i++) {
                float4 o = ((float4*)orow)[i];
                o.x *= f; o.y *= f; o.z *= f; o.w *= f;
                ((float4*)orow)[i] = o;
            }
        }

        // V_i ready. (If K_{i+1} was committed, one group may remain pending.)
        if (have_next) { CP_WAIT(1); } else { CP_WAIT(0); }
        __syncthreads();

        // PV from Vs.
        wmma::fragment<wmma::matrix_a, 16, 16, 8, wmma::precision::tf32, wmma::row_major> pf[16];
        #pragma unroll
        for (int kk = 0; kk < 16; kk++)
            wmma::load_matrix_sync(pf[kk], &Ps[(wm * 16) * 132 + kk * 8], 132);
        #pragma unroll
        for (int n = 0; n < 4; n++) {
            wmma::fragment<wmma::accumulator, 16, 16, 8, float> cfr;
            wmma::load_matrix_sync(cfr, &Os[(wm * 16) * 132 + wn * 64 + n * 16],
                                   132, wmma::mem_row_major);
            #pragma unroll
            for (int kk = 0; kk < 16; kk++) {
                wmma::fragment<wmma::matrix_b, 16, 16, 8, wmma::precision::tf32, wmma::row_major> bf;
                wmma::load_matrix_sync(bf, &Vs[(kk * 8) * 132 + wn * 64 + n * 16], 132);
                wmma::mma_sync(cfr, pf[kk], bf, cfr);
            }
            wmma::store_matrix_sync(&Os[(wm * 16) * 132 + wn * 64 + n * 16],
                                    cfr, 132, wmma::mem_row_major);
        }
        __syncthreads();     // Vs fully consumed

        // Prefetch next V into Vs.
        if (have_next) { ATTN_LOAD_V(kt + 128); CP_COMMIT(); }
    }

    #pragma unroll
    for (int it = 0; it < 8; it++) {
        int idx4 = tid + it * 256;
        int r = idx4 >> 5, c4 = idx4 & 31;
        float inv = 1.0f / lrow[r];
        float4 v = *(float4*)&Os[r * 132 + c4 * 4];
        v.x = tf32r(v.x * inv); v.y = tf32r(v.y * inv);
        v.z = tf32r(v.z * inv); v.w = tf32r(v.w * inv);
        size_t gaddr = ((size_t)(b * S_TOT + q0 + r)) * DIM_ + hd0 + c4 * 4;
        *(float4*)&oj[gaddr] = v;
    }
}

// ---------------------------------------------------------------------------
extern "C" void kernel_launch(void* const* d_in, const int* in_sizes, int n_in,
                              void* d_out, int out_size)
{
    const float* x    = (const float*)d_in[0];
    const float* ctx  = (const float*)d_in[1];
    const float* cosr = (const float*)d_in[2];
    const float* sinr = (const float*)d_in[3];
    const float* wq   = (const float*)d_in[4];
    const float* bq   = (const float*)d_in[5];
    const float* wk   = (const float*)d_in[6];
    const float* bk   = (const float*)d_in[7];
    const float* wv   = (const float*)d_in[8];
    const float* bv   = (const float*)d_in[9];
    const float* wqc  = (const float*)d_in[10];
    const float* bqc  = (const float*)d_in[11];
    const float* wkc  = (const float*)d_in[12];
    const float* bkc  = (const float*)d_in[13];
    const float* wvc  = (const float*)d_in[14];
    const float* bvc  = (const float*)d_in[15];
    const float* w_out     = (const float*)d_in[16];
    const float* b_out     = (const float*)d_in[17];
    const float* w_add_out = (const float*)d_in[18];
    const float* b_add_out = (const float*)d_in[19];
    const float* gq  = (const float*)d_in[20];
    const float* gk  = (const float*)d_in[21];
    const float* gqc = (const float*)d_in[22];
    const float* gkc = (const float*)d_in[23];
    float* out = (float*)d_out;

    float *qj, *kj, *vj, *oj, *wr, *xr, *cr;
    cudaGetSymbolAddress((void**)&qj, g_qj);
    cudaGetSymbolAddress((void**)&kj, g_kj);
    cudaGetSymbolAddress((void**)&vj, g_vj);
    cudaGetSymbolAddress((void**)&oj, g_oj);
    cudaGetSymbolAddress((void**)&wr, g_wr);
    cudaGetSymbolAddress((void**)&xr, g_xr);
    cudaGetSymbolAddress((void**)&cr, g_cr);

    cudaFuncSetAttribute(gemm_tf32, cudaFuncAttributeMaxDynamicSharedMemorySize,
                         GEMM_SMEM_BYTES);
    cudaFuncSetAttribute(attn_kernel, cudaFuncAttributeMaxDynamicSharedMemorySize,
                         ATTN_SMEM_BYTES);

    // --- Pre-pass: round weights + activations to tf32 ---
    RoundSrc8 rs;
    rs.s[0] = wq;  rs.s[1] = wk;  rs.s[2] = wv;
    rs.s[3] = wqc; rs.s[4] = wkc; rs.s[5] = wvc;
    rs.s[6] = w_out; rs.s[7] = w_add_out;
    round_w_kernel<<<dim3(W_ELEMS / 4 / 256, 8), 256>>>(rs, wr);
    round_kernel<<<BATCH * 1024 * DIM_ / 4 / 256, 256>>>(x, xr);
    round_kernel<<<BATCH * 512 * DIM_ / 4 / 256, 256>>>(ctx, cr);

    // --- Merged QKV GEMMs (6 jobs in one launch), BN=256 ---
    GemmJobs6 qkv;
    qkv.j[0] = { xr, wr + 0 * (size_t)W_ELEMS, bq, qj, 2048, 2048, 0, 1024, 1536, 512, 16, 0 };
    qkv.j[1] = { xr, wr + 1 * (size_t)W_ELEMS, bk, kj, 2048, 2048, 0, 1024, 1536, 512, 16, 0 };
    qkv.j[2] = { xr, wr + 2 * (size_t)W_ELEMS, bv, vj, 2048, 2048, 0, 1024, 1536, 512, 16, 1 };
    qkv.j[3] = { cr, wr + 3 * (size_t)W_ELEMS, bqc, qj, 1024, 1024, 0, 512, 1536, 0, 8, 0 };
    qkv.j[4] = { cr, wr + 4 * (size_t)W_ELEMS, bkc, kj, 1024, 1024, 0, 512, 1536, 0, 8, 0 };
    qkv.j[5] = { cr, wr + 5 * (size_t)W_ELEMS, bvc, vj, 1024, 1024, 0, 512, 1536, 0, 8, 1 };
    gemm_tf32<<<dim3(12, 16, 6), 256, GEMM_SMEM_BYTES>>>(qkv);

    // --- RMS norm + RoPE ---
    rms_rope_kernel<<<dim3(S_TOT, BATCH, 2), dim3(128)>>>(qj, kj, cosr, sinr, gq, gk, gqc, gkc);

    // --- Attention ---
    attn_kernel<<<dim3(S_TOT / 64, HEADS_, BATCH), 256, ATTN_SMEM_BYTES>>>(qj, kj, vj, oj);

    // --- Merged output projections (2 jobs) ---
    GemmJobs6 outp;
    outp.j[0] = { oj, wr + 7 * (size_t)W_ELEMS, b_add_out, out,
                  512, 1536, 0, 1024, 1024, 0, 8, 0 };
    outp.j[1] = { oj, wr + 6 * (size_t)W_ELEMS, b_out, out + (size_t)BATCH * S_TXT_ * DIM_,
                  1024, 1536, 512, 2048, 2048, 0, 16, 0 };
    outp.j[2] = outp.j[0]; outp.j[3] = outp.j[0]; outp.j[4] = outp.j[0]; outp.j[5] = outp.j[0];
    gemm_tf32<<<dim3(12, 16, 2), 256, GEMM_SMEM_BYTES>>>(outp);
}

// round 13
// speedup vs baseline: 5.8989x; 3.0155x over previous
#include <cstdint>
#include <cuda_runtime.h>
#include <cuda_fp16.h>
#include <mma.h>

using namespace nvcuda;

#define DIM_   3072
#define S_TOT  1536
#define S_TXT_ 512
#define BATCH  2
#define HD_    128
#define HEADS_ 24
#define SCALE_ 0.08838834764831845f   // 1/sqrt(128)
#define QSCALE_ (SCALE_ * 1.4426950408889634f)   // fold log2(e) for exp2 softmax

#define JOINT_ELEMS (BATCH * S_TOT * DIM_)   // 9,437,184
#define W_ELEMS (DIM_ * DIM_)                // 9,437,184

// Scratch (no allocations allowed) — ALL half now (same 10-bit mantissa as tf32).
__device__ __half g_qj[JOINT_ELEMS];
__device__ __half g_kj[JOINT_ELEMS];
__device__ __half g_vj[JOINT_ELEMS];
__device__ __half g_oj[JOINT_ELEMS];
__device__ __half g_wr[8 * W_ELEMS];          // fp16-rounded weights [K,N]
__device__ __half g_xr[BATCH * 1024 * DIM_];  // fp16-rounded x
__device__ __half g_cr[BATCH * 512 * DIM_];   // fp16-rounded ctx

__device__ __forceinline__ void cp_async16(void* smem_dst, const void* gmem_src) {
    unsigned int d = (unsigned int)__cvta_generic_to_shared(smem_dst);
    asm volatile("cp.async.cg.shared.global [%0], [%1], 16;\n" :: "r"(d), "l"(gmem_src));
}
#define CP_COMMIT() asm volatile("cp.async.commit_group;\n")
#define CP_WAIT(n)  asm volatile("cp.async.wait_group %0;\n" :: "n"(n))

// ---------------------------------------------------------------------------
// Pre-pass: round tensors to fp16 once.
// ---------------------------------------------------------------------------
struct RoundSrc8 { const float* s[8]; };

__global__ void __launch_bounds__(256) round_w_kernel(RoundSrc8 rs, __half* __restrict__ dst) {
    int t = blockIdx.x * 256 + threadIdx.x;            // float4 index
    int w = blockIdx.y;
    float4 v = ((const float4*)rs.s[w])[t];
    __half2* d = (__half2*)(dst + (size_t)w * W_ELEMS) + (size_t)t * 2;
    d[0] = __floats2half2_rn(v.x, v.y);
    d[1] = __floats2half2_rn(v.z, v.w);
}

__global__ void __launch_bounds__(256) round_kernel(const float* __restrict__ src,
                                                    __half* __restrict__ dst) {
    int t = blockIdx.x * 256 + threadIdx.x;
    float4 v = ((const float4*)src)[t];
    __half2* d = (__half2*)dst + (size_t)t * 2;
    d[0] = __floats2half2_rn(v.x, v.y);
    d[1] = __floats2half2_rn(v.z, v.w);
}

// ---------------------------------------------------------------------------
// FP16 GEMM v5: BM=128, BN=256, BK=32, 256 threads (8 warps, 2x4 warp grid,
// warp tile 64x64). m16n16k16 fragments -> 32 HMMA per buffer (vs 64 tf32).
// Loop smem (halfs): As 2*128*40=10240, Bs 2*32*264=16896 -> 54272 B.
// Epilogue smem: Cs 128*260 floats = 133120 B (allocation size).
// ---------------------------------------------------------------------------
#define GEMM_SMEM_BYTES (33280 * 4)

struct GemmJob {
    const __half* A; const __half* W; const float* bias; void* C;
    int in_rpb, in_bsr, in_off;
    int out_rpb, out_bsr, out_off;
    int grid_y, out_float;
};
struct GemmJobs6 { GemmJob j[6]; };

__global__ void __launch_bounds__(256) gemm_fp16(GemmJobs6 jobs)
{
    const GemmJob jb = jobs.j[blockIdx.z];
    if ((int)blockIdx.y >= jb.grid_y) return;

    extern __shared__ char smc[];
    __half* As = (__half*)smc;                 // 2 buffers of 128*40 halfs
    __half* Bs = (__half*)smc + 2 * 128 * 40;  // 2 buffers of 32*264 halfs

    const __half* __restrict__ A = jb.A;
    const __half* __restrict__ W = jb.W;

    const int tid  = threadIdx.x;
    const int warp = tid >> 5;
    const int wm   = warp >> 2;     // 0..1 : row block of 64
    const int wn   = warp & 3;      // 0..3 : col block of 64
    const int m0   = blockIdx.y * 128;
    const int n0   = blockIdx.x * 256;
    const int in_base  = (m0 / jb.in_rpb) * jb.in_bsr + jb.in_off + (m0 % jb.in_rpb);
    const int out_base = (m0 / jb.out_rpb) * jb.out_bsr + jb.out_off + (m0 % jb.out_rpb);

    wmma::fragment<wmma::accumulator, 16, 16, 16, float> cf[4][4];
    #pragma unroll
    for (int i = 0; i < 4; i++)
        #pragma unroll
        for (int j = 0; j < 4; j++)
            wmma::fill_fragment(cf[i][j], 0.0f);

    // ---- prefetch of one BK=32 tile (halfs) into buffer bufi ----
    // A: 128 rows x 32 halfs = 4 chunks/row -> 512 chunks, 2/thread.
    // B: 32 rows x 256 halfs = 32 chunks/row -> 1024 chunks, 4/thread.
    #define GEMM_PREFETCH(k0, bufi) do {                                          \
        __half* Ad = As + (bufi) * (128 * 40);                                    \
        __half* Bd = Bs + (bufi) * (32 * 264);                                    \
        _Pragma("unroll")                                                         \
        for (int it = 0; it < 2; it++) {                                          \
            int idx = tid + it * 256;                                             \
            int r = idx >> 2, c = idx & 3;                                        \
            cp_async16(&Ad[r * 40 + c * 8],                                       \
                       &A[(size_t)(in_base + r) * DIM_ + (k0) + c * 8]);          \
        }                                                                         \
        _Pragma("unroll")                                                         \
        for (int it = 0; it < 4; it++) {                                          \
            int idx = tid + it * 256;                                             \
            int r = idx >> 5, c = idx & 31;                                       \
            cp_async16(&Bd[r * 264 + c * 8],                                      \
                       &W[(size_t)((k0) + r) * DIM_ + n0 + c * 8]);               \
        }                                                                         \
    } while (0)

    GEMM_PREFETCH(0, 0);
    CP_COMMIT();

    int buf = 0;
    for (int t = 0; t < DIM_ / 32; t++) {
        if (t + 1 < DIM_ / 32) GEMM_PREFETCH((t + 1) * 32, buf ^ 1);
        CP_COMMIT();
        CP_WAIT(1);
        __syncthreads();

        __half* Ab = As + buf * (128 * 40);
        __half* Bb = Bs + buf * (32 * 264);

        #pragma unroll
        for (int kk = 0; kk < 32; kk += 16) {
            wmma::fragment<wmma::matrix_a, 16, 16, 16, __half, wmma::row_major> af[4];
            wmma::fragment<wmma::matrix_b, 16, 16, 16, __half, wmma::row_major> bf[4];
            #pragma unroll
            for (int i = 0; i < 4; i++)
                wmma::load_matrix_sync(af[i], &Ab[(wm * 64 + i * 16) * 40 + kk], 40);
            #pragma unroll
            for (int j = 0; j < 4; j++)
                wmma::load_matrix_sync(bf[j], &Bb[kk * 264 + wn * 64 + j * 16], 264);
            #pragma unroll
            for (int i = 0; i < 4; i++)
                #pragma unroll
                for (int j = 0; j < 4; j++)
                    wmma::mma_sync(cf[i][j], af[i], bf[j], cf[i][j]);
        }
        __syncthreads();
        buf ^= 1;
    }

    // Epilogue: stage through smem (fp32), add bias, store half or float.
    float* Cs = (float*)smc;   // 128 x 260
    #pragma unroll
    for (int i = 0; i < 4; i++)
        #pragma unroll
        for (int j = 0; j < 4; j++)
            wmma::store_matrix_sync(&Cs[(wm * 64 + i * 16) * 260 + wn * 64 + j * 16],
                                    cf[i][j], 260, wmma::mem_row_major);
    __syncthreads();

    #pragma unroll
    for (int it = 0; it < 32; it++) {
        int idx4 = tid + it * 256;      // 0..8191 (128 rows x 64 float4)
        int r = idx4 >> 6, c4 = idx4 & 63;
        float4 v  = *(float4*)&Cs[r * 260 + c4 * 4];
        float4 bb = *(const float4*)&jb.bias[n0 + c4 * 4];
        v.x += bb.x; v.y += bb.y; v.z += bb.z; v.w += bb.w;
        size_t off = (size_t)(out_base + r) * DIM_ + n0 + c4 * 4;
        if (jb.out_float) {
            *(float4*)((float*)jb.C + off) = v;
        } else {
            __half2 h0 = __floats2half2_rn(v.x, v.y);
            __half2 h1 = __floats2half2_rn(v.z, v.w);
            __half2* dst = (__half2*)((__half*)jb.C + off);
            dst[0] = h0; dst[1] = h1;
        }
    }
}

// ---------------------------------------------------------------------------
// Fused RMSNorm + RoPE, in-place on joint half Q (z=0) and K (z=1).
// ---------------------------------------------------------------------------
__global__ void __launch_bounds__(128) rms_rope_kernel(
    __half* __restrict__ q, __half* __restrict__ k,
    const float* __restrict__ cosr, const float* __restrict__ sinr,
    const float* __restrict__ gq, const float* __restrict__ gk,
    const float* __restrict__ gqc, const float* __restrict__ gkc)
{
    const int j = blockIdx.x, b = blockIdx.y, which = blockIdx.z;
    __half* buf = which ? k : q;
    const float* g = which ? (j < S_TXT_ ? gkc : gk)
                           : (j < S_TXT_ ? gqc : gq);
    const int lane = threadIdx.x & 31;
    const int warp = threadIdx.x >> 5;
    const size_t rowbase = ((size_t)(b * S_TOT + j)) * DIM_;

    const float c0 = cosr[j * 64 + lane];
    const float s0 = sinr[j * 64 + lane];
    const float c1 = cosr[j * 64 + lane + 32];
    const float s1 = sinr[j * 64 + lane + 32];

    for (int h = warp; h < HEADS_; h += 4) {
        __half* p = buf + rowbase + h * HD_;
        float2 e0 = __half22float2(*(__half2*)&p[2 * lane]);
        float2 e1 = __half22float2(*(__half2*)&p[2 * (lane + 32)]);
        float ss = e0.x * e0.x + e0.y * e0.y + e1.x * e1.x + e1.y * e1.y;
        #pragma unroll
        for (int o = 16; o; o >>= 1) ss += __shfl_xor_sync(0xffffffffu, ss, o);
        float inv = rsqrtf(ss * (1.0f / 128.0f) + 1e-6f);

        float x1 = e0.x * inv * g[2 * lane];
        float x2 = e0.y * inv * g[2 * lane + 1];
        float y1 = e1.x * inv * g[2 * (lane + 32)];
        float y2 = e1.y * inv * g[2 * (lane + 32) + 1];

        *(__half2*)&p[2 * lane] =
            __floats2half2_rn(x1 * c0 - x2 * s0, x1 * s0 + x2 * c0);
        *(__half2*)&p[2 * (lane + 32)] =
            __floats2half2_rn(y1 * c1 - y2 * s1, y1 * s1 + y2 * c1);
    }
}

// ---------------------------------------------------------------------------
// Flash-style attention v5 (fp16 operands, fp32 accum/softmax).
// smem layout (bytes):
//   Ksh  half 128x136 : [0, 34816)
//   Vsh  half 128x136 : [34816, 69632)
//   Psh  half  64x136 : [69632, 87040)   (Q staging, then P)
//   Ss   f32   64x132 : [87040, 120832)  (scores)
//   Os   f32   64x132 : [120832, 154624)
//   mrow/lrow f32 64+64: [154624, 155136)
// ---------------------------------------------------------------------------
#define ATTN_SMEM_BYTES 155136

__global__ void __launch_bounds__(256) attn_kernel(
    const __half* __restrict__ qj, const __half* __restrict__ kj,
    const __half* __restrict__ vj, __half* __restrict__ oj)
{
    extern __shared__ char smc[];
    __half* Ksh = (__half*)smc;                   // ld 136
    __half* Vsh = (__half*)(smc + 34816);         // ld 136
    __half* Psh = (__half*)(smc + 69632);         // ld 136
    float*  Ss  = (float*)(smc + 87040);          // ld 132
    float*  Os  = (float*)(smc + 120832);         // ld 132
    float*  mrow = (float*)(smc + 154624);        // 64
    float*  lrow = (float*)(smc + 154624 + 256);  // 64

    const int tid  = threadIdx.x;
    const int warp = tid >> 5;
    const int wm   = warp >> 1;       // 0..3 : 16-row block
    const int wn   = warp & 1;        // 0..1 : 64-col block
    const int q0   = blockIdx.x * 64;
    const int h    = blockIdx.y;
    const int b    = blockIdx.z;
    const size_t hd0 = (size_t)h * HD_;

    // K/V tile = 128 rows x 128 halfs = 2048 16B chunks -> 8 iters.
    #define ATTN_LOAD_K(kt) do {                                                  \
        _Pragma("unroll")                                                         \
        for (int it = 0; it < 8; it++) {                                          \
            int idx = tid + it * 256;                                             \
            int r = idx >> 4, c = idx & 15;                                       \
            size_t gaddr = ((size_t)(b * S_TOT + (kt) + r)) * DIM_ + hd0 + c * 8; \
            cp_async16(&Ksh[r * 136 + c * 8], &kj[gaddr]);                        \
        }                                                                         \
    } while (0)
    #define ATTN_LOAD_V(kt) do {                                                  \
        _Pragma("unroll")                                                         \
        for (int it = 0; it < 8; it++) {                                          \
            int idx = tid + it * 256;                                             \
            int r = idx >> 4, c = idx & 15;                                       \
            size_t gaddr = ((size_t)(b * S_TOT + (kt) + r)) * DIM_ + hd0 + c * 8; \
            cp_async16(&Vsh[r * 136 + c * 8], &vj[gaddr]);                        \
        }                                                                         \
    } while (0)

    // Prologue: start K0 / V0 transfers, then stage Q while they fly.
    ATTN_LOAD_K(0); CP_COMMIT();
    ATTN_LOAD_V(0); CP_COMMIT();

    // Q staging (half, scaled by QSCALE): 64 rows x 64 half2 = 4096, 16/thread.
    #pragma unroll
    for (int it = 0; it < 16; it++) {
        int idx = tid + it * 256;
        int r = idx >> 6, c2 = idx & 63;
        size_t gaddr = ((size_t)(b * S_TOT + q0 + r)) * DIM_ + hd0 + c2 * 2;
        float2 v = __half22float2(*(const __half2*)&qj[gaddr]);
        *(__half2*)&Psh[r * 136 + c2 * 2] =
            __floats2half2_rn(v.x * QSCALE_, v.y * QSCALE_);
    }
    // Init O and stats.
    #pragma unroll
    for (int it = 0; it < 8; it++) {
        int idx4 = tid + it * 256;
        int r = idx4 >> 5, c4 = idx4 & 31;
        *(float4*)&Os[r * 132 + c4 * 4] = make_float4(0.f, 0.f, 0.f, 0.f);
    }
    if (tid < 64) { mrow[tid] = -1e30f; lrow[tid] = 0.f; }
    __syncthreads();

    // Preload Q fragments for this warp's 16 rows (8 k-chunks of 16).
    wmma::fragment<wmma::matrix_a, 16, 16, 16, __half, wmma::row_major> qf[8];
    #pragma unroll
    for (int t = 0; t < 8; t++)
        wmma::load_matrix_sync(qf[t], &Psh[(wm * 16) * 136 + t * 16], 136);
    __syncthreads();  // Psh reused for P

    const int r_sm = tid >> 2;
    const int sub  = tid & 3;

    for (int kt = 0; kt < S_TOT; kt += 128) {
        const bool have_next = (kt + 128 < S_TOT);

        // K_i ready (V_i may still be in flight).
        CP_WAIT(1);
        __syncthreads();

        // Scores -> Ss (fp32).
        #pragma unroll
        for (int n = 0; n < 4; n++) {
            wmma::fragment<wmma::accumulator, 16, 16, 16, float> cfr;
            wmma::fill_fragment(cfr, 0.0f);
            #pragma unroll
            for (int kk = 0; kk < 8; kk++) {
                wmma::fragment<wmma::matrix_b, 16, 16, 16, __half, wmma::col_major> bf;
                wmma::load_matrix_sync(bf, &Ksh[(wn * 64 + n * 16) * 136 + kk * 16], 136);
                wmma::mma_sync(cfr, qf[kk], bf, cfr);
            }
            wmma::store_matrix_sync(&Ss[(wm * 16) * 132 + wn * 64 + n * 16],
                                    cfr, 132, wmma::mem_row_major);
        }
        __syncthreads();     // Ksh fully consumed

        // Prefetch next K while softmax runs.
        if (have_next) { ATTN_LOAD_K(kt + 128); CP_COMMIT(); }

        // Online softmax (log2 domain): read Ss fp32, write P half to Psh.
        {
            float* srow = &Ss[r_sm * 132 + sub * 32];
            float mx = -1e30f;
            float4 vv[8];
            #pragma unroll
            for (int i = 0; i < 8; i++) {
                vv[i] = ((float4*)srow)[i];
                mx = fmaxf(mx, fmaxf(fmaxf(vv[i].x, vv[i].y), fmaxf(vv[i].z, vv[i].w)));
            }
            mx = fmaxf(mx, __shfl_xor_sync(0xffffffffu, mx, 1));
            mx = fmaxf(mx, __shfl_xor_sync(0xffffffffu, mx, 2));
            float mold = mrow[r_sm];
            float newm = fmaxf(mold, mx);
            float f = exp2f(mold - newm);
            float sum = 0.f;
            __half2* prow = (__half2*)&Psh[r_sm * 136 + sub * 32];
            #pragma unroll
            for (int i = 0; i < 8; i++) {
                vv[i].x = exp2f(vv[i].x - newm);
                vv[i].y = exp2f(vv[i].y - newm);
                vv[i].z = exp2f(vv[i].z - newm);
                vv[i].w = exp2f(vv[i].w - newm);
                sum += vv[i].x + vv[i].y + vv[i].z + vv[i].w;
                prow[2 * i]     = __floats2half2_rn(vv[i].x, vv[i].y);
                prow[2 * i + 1] = __floats2half2_rn(vv[i].z, vv[i].w);
            }
            sum += __shfl_xor_sync(0xffffffffu, sum, 1);
            sum += __shfl_xor_sync(0xffffffffu, sum, 2);
            if (sub == 0) { lrow[r_sm] = lrow[r_sm] * f + sum; mrow[r_sm] = newm; }
            // Rescale O.
            float* orow = &Os[r_sm * 132 + sub * 32];
            #pragma unroll
            for (int i = 0; i < 8; i++) {
                float4 o = ((float4*)orow)[i];
                o.x *= f; o.y *= f; o.z *= f; o.w *= f;
                ((float4*)orow)[i] = o;
            }
        }

        // V_i ready.
        if (have_next) { CP_WAIT(1); } else { CP_WAIT(0); }
        __syncthreads();

        // PV: O += P @ V.
        wmma::fragment<wmma::matrix_a, 16, 16, 16, __half, wmma::row_major> pf[8];
        #pragma unroll
        for (int kk = 0; kk < 8; kk++)
            wmma::load_matrix_sync(pf[kk], &Psh[(wm * 16) * 136 + kk * 16], 136);
        #pragma unroll
        for (int n = 0; n < 4; n++) {
            wmma::fragment<wmma::accumulator, 16, 16, 16, float> cfr;
            wmma::load_matrix_sync(cfr, &Os[(wm * 16) * 132 + wn * 64 + n * 16],
                                   132, wmma::mem_row_major);
            #pragma unroll
            for (int kk = 0; kk < 8; kk++) {
                wmma::fragment<wmma::matrix_b, 16, 16, 16, __half, wmma::row_major> bf;
                wmma::load_matrix_sync(bf, &Vsh[(kk * 16) * 136 + wn * 64 + n * 16], 136);
                wmma::mma_sync(cfr, pf[kk], bf, cfr);
            }
            wmma::store_matrix_sync(&Os[(wm * 16) * 132 + wn * 64 + n * 16],
                                    cfr, 132, wmma::mem_row_major);
        }
        __syncthreads();     // Vsh fully consumed

        // Prefetch next V.
        if (have_next) { ATTN_LOAD_V(kt + 128); CP_COMMIT(); }
    }

    // Writeout: O / l -> half oj.
    #pragma unroll
    for (int it = 0; it < 8; it++) {
        int idx4 = tid + it * 256;
        int r = idx4 >> 5, c4 = idx4 & 31;
        float inv = 1.0f / lrow[r];
        float4 v = *(float4*)&Os[r * 132 + c4 * 4];
        size_t gaddr = ((size_t)(b * S_TOT + q0 + r)) * DIM_ + hd0 + c4 * 4;
        __half2* dst = (__half2*)&oj[gaddr];
        dst[0] = __floats2half2_rn(v.x * inv, v.y * inv);
        dst[1] = __floats2half2_rn(v.z * inv, v.w * inv);
    }
}

// ---------------------------------------------------------------------------
extern "C" void kernel_launch(void* const* d_in, const int* in_sizes, int n_in,
                              void* d_out, int out_size)
{
    const float* x    = (const float*)d_in[0];
    const float* ctx  = (const float*)d_in[1];
    const float* cosr = (const float*)d_in[2];
    const float* sinr = (const float*)d_in[3];
    const float* wq   = (const float*)d_in[4];
    const float* bq   = (const float*)d_in[5];
    const float* wk   = (const float*)d_in[6];
    const float* bk   = (const float*)d_in[7];
    const float* wv   = (const float*)d_in[8];
    const float* bv   = (const float*)d_in[9];
    const float* wqc  = (const float*)d_in[10];
    const float* bqc  = (const float*)d_in[11];
    const float* wkc  = (const float*)d_in[12];
    const float* bkc  = (const float*)d_in[13];
    const float* wvc  = (const float*)d_in[14];
    const float* bvc  = (const float*)d_in[15];
    const float* w_out     = (const float*)d_in[16];
    const float* b_out     = (const float*)d_in[17];
    const float* w_add_out = (const float*)d_in[18];
    const float* b_add_out = (const float*)d_in[19];
    const float* gq  = (const float*)d_in[20];
    const float* gk  = (const float*)d_in[21];
    const float* gqc = (const float*)d_in[22];
    const float* gkc = (const float*)d_in[23];
    float* out = (float*)d_out;

    __half *qj, *kj, *vj, *oj, *wr, *xr, *cr;
    cudaGetSymbolAddress((void**)&qj, g_qj);
    cudaGetSymbolAddress((void**)&kj, g_kj);
    cudaGetSymbolAddress((void**)&vj, g_vj);
    cudaGetSymbolAddress((void**)&oj, g_oj);
    cudaGetSymbolAddress((void**)&wr, g_wr);
    cudaGetSymbolAddress((void**)&xr, g_xr);
    cudaGetSymbolAddress((void**)&cr, g_cr);

    cudaFuncSetAttribute(gemm_fp16, cudaFuncAttributeMaxDynamicSharedMemorySize,
                         GEMM_SMEM_BYTES);
    cudaFuncSetAttribute(attn_kernel, cudaFuncAttributeMaxDynamicSharedMemorySize,
                         ATTN_SMEM_BYTES);

    // --- Pre-pass: round weights + activations to fp16 ---
    RoundSrc8 rs;
    rs.s[0] = wq;  rs.s[1] = wk;  rs.s[2] = wv;
    rs.s[3] = wqc; rs.s[4] = wkc; rs.s[5] = wvc;
    rs.s[6] = w_out; rs.s[7] = w_add_out;
    round_w_kernel<<<dim3(W_ELEMS / 4 / 256, 8), 256>>>(rs, wr);
    round_kernel<<<BATCH * 1024 * DIM_ / 4 / 256, 256>>>(x, xr);
    round_kernel<<<BATCH * 512 * DIM_ / 4 / 256, 256>>>(ctx, cr);

    // --- Merged QKV GEMMs (6 jobs in one launch), BN=256 ---
    GemmJobs6 qkv;
    qkv.j[0] = { xr, wr + 0 * (size_t)W_ELEMS, bq, qj, 2048, 2048, 0, 1024, 1536, 512, 16, 0 };
    qkv.j[1] = { xr, wr + 1 * (size_t)W_ELEMS, bk, kj, 2048, 2048, 0, 1024, 1536, 512, 16, 0 };
    qkv.j[2] = { xr, wr + 2 * (size_t)W_ELEMS, bv, vj, 2048, 2048, 0, 1024, 1536, 512, 16, 0 };
    qkv.j[3] = { cr, wr + 3 * (size_t)W_ELEMS, bqc, qj, 1024, 1024, 0, 512, 1536, 0, 8, 0 };
    qkv.j[4] = { cr, wr + 4 * (size_t)W_ELEMS, bkc, kj, 1024, 1024, 0, 512, 1536, 0, 8, 0 };
    qkv.j[5] = { cr, wr + 5 * (size_t)W_ELEMS, bvc, vj, 1024, 1024, 0, 512, 1536, 0, 8, 0 };
    gemm_fp16<<<dim3(12, 16, 6), 256, GEMM_SMEM_BYTES>>>(qkv);

    // --- RMS norm + RoPE (half in/out) ---
    rms_rope_kernel<<<dim3(S_TOT, BATCH, 2), dim3(128)>>>(qj, kj, cosr, sinr, gq, gk, gqc, gkc);

    // --- Attention (fp16 operands) ---
    attn_kernel<<<dim3(S_TOT / 64, HEADS_, BATCH), 256, ATTN_SMEM_BYTES>>>(qj, kj, vj, oj);

    // --- Merged output projections (2 jobs, float output) ---
    GemmJobs6 outp;
    outp.j[0] = { oj, wr + 7 * (size_t)W_ELEMS, b_add_out, out,
                  512, 1536, 0, 1024, 1024, 0, 8, 1 };
    outp.j[1] = { oj, wr + 6 * (size_t)W_ELEMS, b_out, out + (size_t)BATCH * S_TXT_ * DIM_,
                  1024, 1536, 512, 2048, 2048, 0, 16, 1 };
    outp.j[2] = outp.j[0]; outp.j[3] = outp.j[0]; outp.j[4] = outp.j[0]; outp.j[5] = outp.j[0];
    gemm_fp16<<<dim3(12, 16, 2), 256, GEMM_SMEM_BYTES>>>(outp);
}

// round 14
// speedup vs baseline: 6.2179x; 1.0541x over previous
#include <cstdint>
#include <cuda_runtime.h>
#include <cuda_fp16.h>
#include <mma.h>

using namespace nvcuda;

#define DIM_   3072
#define S_TOT  1536
#define S_TXT_ 512
#define BATCH  2
#define HD_    128
#define HEADS_ 24
#define SCALE_ 0.08838834764831845f   // 1/sqrt(128)
#define QSCALE_ (SCALE_ * 1.4426950408889634f)   // fold log2(e) for exp2 softmax

#define JOINT_ELEMS (BATCH * S_TOT * DIM_)   // 9,437,184
#define W_ELEMS (DIM_ * DIM_)                // 9,437,184

// Scratch (no allocations allowed) — all half (same 10-bit mantissa as tf32).
__device__ __half g_qj[JOINT_ELEMS];
__device__ __half g_kj[JOINT_ELEMS];
__device__ __half g_vj[JOINT_ELEMS];
__device__ __half g_oj[JOINT_ELEMS];
__device__ __half g_wr[8 * W_ELEMS];          // fp16-rounded weights [K,N]
__device__ __half g_xr[BATCH * 1024 * DIM_];  // fp16-rounded x
__device__ __half g_cr[BATCH * 512 * DIM_];   // fp16-rounded ctx

__device__ __forceinline__ void cp_async16(void* smem_dst, const void* gmem_src) {
    unsigned int d = (unsigned int)__cvta_generic_to_shared(smem_dst);
    asm volatile("cp.async.cg.shared.global [%0], [%1], 16;\n" :: "r"(d), "l"(gmem_src));
}
#define CP_COMMIT() asm volatile("cp.async.commit_group;\n")
#define CP_WAIT(n)  asm volatile("cp.async.wait_group %0;\n" :: "n"(n))

// ---------------------------------------------------------------------------
// Pre-pass: round tensors to fp16 once.
// ---------------------------------------------------------------------------
struct RoundSrc8 { const float* s[8]; };

__global__ void __launch_bounds__(256) round_w_kernel(RoundSrc8 rs, __half* __restrict__ dst) {
    int t = blockIdx.x * 256 + threadIdx.x;            // float4 index
    int w = blockIdx.y;
    float4 v = ((const float4*)rs.s[w])[t];
    __half2* d = (__half2*)(dst + (size_t)w * W_ELEMS) + (size_t)t * 2;
    d[0] = __floats2half2_rn(v.x, v.y);
    d[1] = __floats2half2_rn(v.z, v.w);
}

__global__ void __launch_bounds__(256) round_kernel(const float* __restrict__ src,
                                                    __half* __restrict__ dst) {
    int t = blockIdx.x * 256 + threadIdx.x;
    float4 v = ((const float4*)src)[t];
    __half2* d = (__half2*)dst + (size_t)t * 2;
    d[0] = __floats2half2_rn(v.x, v.y);
    d[1] = __floats2half2_rn(v.z, v.w);
}

// ---------------------------------------------------------------------------
// FP16 GEMM v6: BM=128, BN=256, BK=64, 256 threads (8 warps, 2x4 warp grid,
// warp tile 64x64). 3-stage cp.async pipeline; 64 HMMA per barrier pair,
// 48 iterations (half the barriers of BK=32).
// Per stage (halfs): A 128x72 = 18432 B, B 64x264 = 33792 B -> 52224 B.
// 3 stages = 156672 B. Epilogue Cs 128x260 f32 = 133120 B (<= alloc).
// ---------------------------------------------------------------------------
#define GEMM_SMEM_BYTES 156672

struct GemmJob {
    const __half* A; const __half* W; const float* bias; void* C;
    int in_rpb, in_bsr, in_off;
    int out_rpb, out_bsr, out_off;
    int grid_y, out_float;
};
struct GemmJobs6 { GemmJob j[6]; };

__global__ void __launch_bounds__(256) gemm_fp16(GemmJobs6 jobs)
{
    const GemmJob jb = jobs.j[blockIdx.z];
    if ((int)blockIdx.y >= jb.grid_y) return;

    extern __shared__ char smc[];
    // Stage s: A at smc + s*52224, B at smc + s*52224 + 18432.
    const __half* __restrict__ A = jb.A;
    const __half* __restrict__ W = jb.W;

    const int tid  = threadIdx.x;
    const int warp = tid >> 5;
    const int wm   = warp >> 2;     // 0..1 : row block of 64
    const int wn   = warp & 3;      // 0..3 : col block of 64
    const int m0   = blockIdx.y * 128;
    const int n0   = blockIdx.x * 256;
    const int in_base  = (m0 / jb.in_rpb) * jb.in_bsr + jb.in_off + (m0 % jb.in_rpb);
    const int out_base = (m0 / jb.out_rpb) * jb.out_bsr + jb.out_off + (m0 % jb.out_rpb);

    wmma::fragment<wmma::accumulator, 16, 16, 16, float> cf[4][4];
    #pragma unroll
    for (int i = 0; i < 4; i++)
        #pragma unroll
        for (int j = 0; j < 4; j++)
            wmma::fill_fragment(cf[i][j], 0.0f);

    // ---- prefetch one BK=64 tile into stage slot ----
    // A: 128 rows x 64 halfs = 1024 16B chunks -> 4 iters.
    // B: 64 rows x 256 halfs = 2048 chunks -> 8 iters.
    #define GEMM_PREFETCH(k0, slot) do {                                          \
        __half* Ad = (__half*)(smc + (slot) * 52224);                             \
        __half* Bd = (__half*)(smc + (slot) * 52224 + 18432);                     \
        _Pragma("unroll")                                                         \
        for (int it = 0; it < 4; it++) {                                          \
            int idx = tid + it * 256;                                             \
            int r = idx >> 3, c = idx & 7;                                        \
            cp_async16(&Ad[r * 72 + c * 8],                                       \
                       &A[(size_t)(in_base + r) * DIM_ + (k0) + c * 8]);          \
        }                                                                         \
        _Pragma("unroll")                                                         \
        for (int it = 0; it < 8; it++) {                                          \
            int idx = tid + it * 256;                                             \
            int r = idx >> 5, c = idx & 31;                                       \
            cp_async16(&Bd[r * 264 + c * 8],                                      \
                       &W[(size_t)((k0) + r) * DIM_ + n0 + c * 8]);               \
        }                                                                         \
    } while (0)

    #pragma unroll
    for (int s = 0; s < 3; s++) { GEMM_PREFETCH(s * 64, s); CP_COMMIT(); }

    const int NSTAGE = DIM_ / 64;   // 48
    for (int i = 0; i < NSTAGE; i++) {
        CP_WAIT(2);                 // stage i complete (2 younger may pend)
        __syncthreads();

        int slot = i % 3;
        __half* Ab = (__half*)(smc + slot * 52224);
        __half* Bb = (__half*)(smc + slot * 52224 + 18432);

        #pragma unroll
        for (int kk = 0; kk < 64; kk += 16) {
            wmma::fragment<wmma::matrix_a, 16, 16, 16, __half, wmma::row_major> af[4];
            wmma::fragment<wmma::matrix_b, 16, 16, 16, __half, wmma::row_major> bf[4];
            #pragma unroll
            for (int ii = 0; ii < 4; ii++)
                wmma::load_matrix_sync(af[ii], &Ab[(wm * 64 + ii * 16) * 72 + kk], 72);
            #pragma unroll
            for (int jj = 0; jj < 4; jj++)
                wmma::load_matrix_sync(bf[jj], &Bb[kk * 264 + wn * 64 + jj * 16], 264);
            #pragma unroll
            for (int ii = 0; ii < 4; ii++)
                #pragma unroll
                for (int jj = 0; jj < 4; jj++)
                    wmma::mma_sync(cf[ii][jj], af[ii], bf[jj], cf[ii][jj]);
        }
        __syncthreads();            // all warps done with slot before refill

        if (i + 3 < NSTAGE) GEMM_PREFETCH((i + 3) * 64, slot);
        CP_COMMIT();                // keep group count uniform
    }

    // Epilogue: stage through smem (fp32), add bias, store half or float.
    float* Cs = (float*)smc;   // 128 x 260
    #pragma unroll
    for (int i = 0; i < 4; i++)
        #pragma unroll
        for (int j = 0; j < 4; j++)
            wmma::store_matrix_sync(&Cs[(wm * 64 + i * 16) * 260 + wn * 64 + j * 16],
                                    cf[i][j], 260, wmma::mem_row_major);
    __syncthreads();

    #pragma unroll
    for (int it = 0; it < 32; it++) {
        int idx4 = tid + it * 256;      // 0..8191 (128 rows x 64 float4)
        int r = idx4 >> 6, c4 = idx4 & 63;
        float4 v  = *(float4*)&Cs[r * 260 + c4 * 4];
        float4 bb = *(const float4*)&jb.bias[n0 + c4 * 4];
        v.x += bb.x; v.y += bb.y; v.z += bb.z; v.w += bb.w;
        size_t off = (size_t)(out_base + r) * DIM_ + n0 + c4 * 4;
        if (jb.out_float) {
            *(float4*)((float*)jb.C + off) = v;
        } else {
            __half2 h0 = __floats2half2_rn(v.x, v.y);
            __half2 h1 = __floats2half2_rn(v.z, v.w);
            __half2* dst = (__half2*)((__half*)jb.C + off);
            dst[0] = h0; dst[1] = h1;
        }
    }
}

// ---------------------------------------------------------------------------
// Fused RMSNorm + RoPE, in-place on joint half Q (z=0) and K (z=1).
// ---------------------------------------------------------------------------
__global__ void __launch_bounds__(128) rms_rope_kernel(
    __half* __restrict__ q, __half* __restrict__ k,
    const float* __restrict__ cosr, const float* __restrict__ sinr,
    const float* __restrict__ gq, const float* __restrict__ gk,
    const float* __restrict__ gqc, const float* __restrict__ gkc)
{
    const int j = blockIdx.x, b = blockIdx.y, which = blockIdx.z;
    __half* buf = which ? k : q;
    const float* g = which ? (j < S_TXT_ ? gkc : gk)
                           : (j < S_TXT_ ? gqc : gq);
    const int lane = threadIdx.x & 31;
    const int warp = threadIdx.x >> 5;
    const size_t rowbase = ((size_t)(b * S_TOT + j)) * DIM_;

    const float c0 = cosr[j * 64 + lane];
    const float s0 = sinr[j * 64 + lane];
    const float c1 = cosr[j * 64 + lane + 32];
    const float s1 = sinr[j * 64 + lane + 32];

    for (int h = warp; h < HEADS_; h += 4) {
        __half* p = buf + rowbase + h * HD_;
        float2 e0 = __half22float2(*(__half2*)&p[2 * lane]);
        float2 e1 = __half22float2(*(__half2*)&p[2 * (lane + 32)]);
        float ss = e0.x * e0.x + e0.y * e0.y + e1.x * e1.x + e1.y * e1.y;
        #pragma unroll
        for (int o = 16; o; o >>= 1) ss += __shfl_xor_sync(0xffffffffu, ss, o);
        float inv = rsqrtf(ss * (1.0f / 128.0f) + 1e-6f);

        float x1 = e0.x * inv * g[2 * lane];
        float x2 = e0.y * inv * g[2 * lane + 1];
        float y1 = e1.x * inv * g[2 * (lane + 32)];
        float y2 = e1.y * inv * g[2 * (lane + 32) + 1];

        *(__half2*)&p[2 * lane] =
            __floats2half2_rn(x1 * c0 - x2 * s0, x1 * s0 + x2 * c0);
        *(__half2*)&p[2 * (lane + 32)] =
            __floats2half2_rn(y1 * c1 - y2 * s1, y1 * s1 + y2 * c1);
    }
}

// ---------------------------------------------------------------------------
// Flash-style attention (fp16 operands, fp32 accum/softmax).
// smem layout (bytes):
//   Ksh  half 128x136 : [0, 34816)
//   Vsh  half 128x136 : [34816, 69632)
//   Psh  half  64x136 : [69632, 87040)   (Q staging, then P)
//   Ss   f32   64x132 : [87040, 120832)  (scores)
//   Os   f32   64x132 : [120832, 154624)
//   mrow/lrow f32 64+64: [154624, 155136)
// ---------------------------------------------------------------------------
#define ATTN_SMEM_BYTES 155136

__global__ void __launch_bounds__(256) attn_kernel(
    const __half* __restrict__ qj, const __half* __restrict__ kj,
    const __half* __restrict__ vj, __half* __restrict__ oj)
{
    extern __shared__ char smc[];
    __half* Ksh = (__half*)smc;                   // ld 136
    __half* Vsh = (__half*)(smc + 34816);         // ld 136
    __half* Psh = (__half*)(smc + 69632);         // ld 136
    float*  Ss  = (float*)(smc + 87040);          // ld 132
    float*  Os  = (float*)(smc + 120832);         // ld 132
    float*  mrow = (float*)(smc + 154624);        // 64
    float*  lrow = (float*)(smc + 154624 + 256);  // 64

    const int tid  = threadIdx.x;
    const int warp = tid >> 5;
    const int wm   = warp >> 1;       // 0..3 : 16-row block
    const int wn   = warp & 1;        // 0..1 : 64-col block
    const int q0   = blockIdx.x * 64;
    const int h    = blockIdx.y;
    const int b    = blockIdx.z;
    const size_t hd0 = (size_t)h * HD_;

    // K/V tile = 128 rows x 128 halfs = 2048 16B chunks -> 8 iters.
    #define ATTN_LOAD_K(kt) do {                                                  \
        _Pragma("unroll")                                                         \
        for (int it = 0; it < 8; it++) {                                          \
            int idx = tid + it * 256;                                             \
            int r = idx >> 4, c = idx & 15;                                       \
            size_t gaddr = ((size_t)(b * S_TOT + (kt) + r)) * DIM_ + hd0 + c * 8; \
            cp_async16(&Ksh[r * 136 + c * 8], &kj[gaddr]);                        \
        }                                                                         \
    } while (0)
    #define ATTN_LOAD_V(kt) do {                                                  \
        _Pragma("unroll")                                                         \
        for (int it = 0; it < 8; it++) {                                          \
            int idx = tid + it * 256;                                             \
            int r = idx >> 4, c = idx & 15;                                       \
            size_t gaddr = ((size_t)(b * S_TOT + (kt) + r)) * DIM_ + hd0 + c * 8; \
            cp_async16(&Vsh[r * 136 + c * 8], &vj[gaddr]);                        \
        }                                                                         \
    } while (0)

    // Prologue: start K0 / V0 transfers, then stage Q while they fly.
    ATTN_LOAD_K(0); CP_COMMIT();
    ATTN_LOAD_V(0); CP_COMMIT();

    // Q staging (half, scaled by QSCALE): 64 rows x 64 half2, 16/thread.
    #pragma unroll
    for (int it = 0; it < 16; it++) {
        int idx = tid + it * 256;
        int r = idx >> 6, c2 = idx & 63;
        size_t gaddr = ((size_t)(b * S_TOT + q0 + r)) * DIM_ + hd0 + c2 * 2;
        float2 v = __half22float2(*(const __half2*)&qj[gaddr]);
        *(__half2*)&Psh[r * 136 + c2 * 2] =
            __floats2half2_rn(v.x * QSCALE_, v.y * QSCALE_);
    }
    // Init O and stats.
    #pragma unroll
    for (int it = 0; it < 8; it++) {
        int idx4 = tid + it * 256;
        int r = idx4 >> 5, c4 = idx4 & 31;
        *(float4*)&Os[r * 132 + c4 * 4] = make_float4(0.f, 0.f, 0.f, 0.f);
    }
    if (tid < 64) { mrow[tid] = -1e30f; lrow[tid] = 0.f; }
    __syncthreads();

    // Preload Q fragments for this warp's 16 rows (8 k-chunks of 16).
    wmma::fragment<wmma::matrix_a, 16, 16, 16, __half, wmma::row_major> qf[8];
    #pragma unroll
    for (int t = 0; t < 8; t++)
        wmma::load_matrix_sync(qf[t], &Psh[(wm * 16) * 136 + t * 16], 136);
    __syncthreads();  // Psh reused for P

    const int r_sm = tid >> 2;
    const int sub  = tid & 3;

    for (int kt = 0; kt < S_TOT; kt += 128) {
        const bool have_next = (kt + 128 < S_TOT);

        // K_i ready (V_i may still be in flight).
        CP_WAIT(1);
        __syncthreads();

        // Scores -> Ss (fp32).
        #pragma unroll
        for (int n = 0; n < 4; n++) {
            wmma::fragment<wmma::accumulator, 16, 16, 16, float> cfr;
            wmma::fill_fragment(cfr, 0.0f);
            #pragma unroll
            for (int kk = 0; kk < 8; kk++) {
                wmma::fragment<wmma::matrix_b, 16, 16, 16, __half, wmma::col_major> bf;
                wmma::load_matrix_sync(bf, &Ksh[(wn * 64 + n * 16) * 136 + kk * 16], 136);
                wmma::mma_sync(cfr, qf[kk], bf, cfr);
            }
            wmma::store_matrix_sync(&Ss[(wm * 16) * 132 + wn * 64 + n * 16],
                                    cfr, 132, wmma::mem_row_major);
        }
        __syncthreads();     // Ksh fully consumed

        // Prefetch next K while softmax runs.
        if (have_next) { ATTN_LOAD_K(kt + 128); CP_COMMIT(); }

        // Online softmax (log2 domain): read Ss fp32, write P half to Psh.
        {
            float* srow = &Ss[r_sm * 132 + sub * 32];
            float mx = -1e30f;
            float4 vv[8];
            #pragma unroll
            for (int i = 0; i < 8; i++) {
                vv[i] = ((float4*)srow)[i];
                mx = fmaxf(mx, fmaxf(fmaxf(vv[i].x, vv[i].y), fmaxf(vv[i].z, vv[i].w)));
            }
            mx = fmaxf(mx, __shfl_xor_sync(0xffffffffu, mx, 1));
            mx = fmaxf(mx, __shfl_xor_sync(0xffffffffu, mx, 2));
            float mold = mrow[r_sm];
            float newm = fmaxf(mold, mx);
            float f = exp2f(mold - newm);
            float sum = 0.f;
            __half2* prow = (__half2*)&Psh[r_sm * 136 + sub * 32];
            #pragma unroll
            for (int i = 0; i < 8; i++) {
                vv[i].x = exp2f(vv[i].x - newm);
                vv[i].y = exp2f(vv[i].y - newm);
                vv[i].z = exp2f(vv[i].z - newm);
                vv[i].w = exp2f(vv[i].w - newm);
                sum += vv[i].x + vv[i].y + vv[i].z + vv[i].w;
                prow[2 * i]     = __floats2half2_rn(vv[i].x, vv[i].y);
                prow[2 * i + 1] = __floats2half2_rn(vv[i].z, vv[i].w);
            }
            sum += __shfl_xor_sync(0xffffffffu, sum, 1);
            sum += __shfl_xor_sync(0xffffffffu, sum, 2);
            if (sub == 0) { lrow[r_sm] = lrow[r_sm] * f + sum; mrow[r_sm] = newm; }
            // Rescale O only when the running max actually changed (f != 1).
            if (f != 1.0f) {
                float* orow = &Os[r_sm * 132 + sub * 32];
                #pragma unroll
                for (int i = 0; i < 8; i++) {
                    float4 o = ((float4*)orow)[i];
                    o.x *= f; o.y *= f; o.z *= f; o.w *= f;
                    ((float4*)orow)[i] = o;
                }
            }
        }

        // V_i ready.
        if (have_next) { CP_WAIT(1); } else { CP_WAIT(0); }
        __syncthreads();

        // PV: O += P @ V.
        wmma::fragment<wmma::matrix_a, 16, 16, 16, __half, wmma::row_major> pf[8];
        #pragma unroll
        for (int kk = 0; kk < 8; kk++)
            wmma::load_matrix_sync(pf[kk], &Psh[(wm * 16) * 136 + kk * 16], 136);
        #pragma unroll
        for (int n = 0; n < 4; n++) {
            wmma::fragment<wmma::accumulator, 16, 16, 16, float> cfr;
            wmma::load_matrix_sync(cfr, &Os[(wm * 16) * 132 + wn * 64 + n * 16],
                                   132, wmma::mem_row_major);
            #pragma unroll
            for (int kk = 0; kk < 8; kk++) {
                wmma::fragment<wmma::matrix_b, 16, 16, 16, __half, wmma::row_major> bf;
                wmma::load_matrix_sync(bf, &Vsh[(kk * 16) * 136 + wn * 64 + n * 16], 136);
                wmma::mma_sync(cfr, pf[kk], bf, cfr);
            }
            wmma::store_matrix_sync(&Os[(wm * 16) * 132 + wn * 64 + n * 16],
                                    cfr, 132, wmma::mem_row_major);
        }
        __syncthreads();     // Vsh fully consumed

        // Prefetch next V.
        if (have_next) { ATTN_LOAD_V(kt + 128); CP_COMMIT(); }
    }

    // Writeout: O / l -> half oj.
    #pragma unroll
    for (int it = 0; it < 8; it++) {
        int idx4 = tid + it * 256;
        int r = idx4 >> 5, c4 = idx4 & 31;
        float inv = 1.0f / lrow[r];
        float4 v = *(float4*)&Os[r * 132 + c4 * 4];
        size_t gaddr = ((size_t)(b * S_TOT + q0 + r)) * DIM_ + hd0 + c4 * 4;
        __half2* dst = (__half2*)&oj[gaddr];
        dst[0] = __floats2half2_rn(v.x * inv, v.y * inv);
        dst[1] = __floats2half2_rn(v.z * inv, v.w * inv);
    }
}

// ---------------------------------------------------------------------------
extern "C" void kernel_launch(void* const* d_in, const int* in_sizes, int n_in,
                              void* d_out, int out_size)
{
    const float* x    = (const float*)d_in[0];
    const float* ctx  = (const float*)d_in[1];
    const float* cosr = (const float*)d_in[2];
    const float* sinr = (const float*)d_in[3];
    const float* wq   = (const float*)d_in[4];
    const float* bq   = (const float*)d_in[5];
    const float* wk   = (const float*)d_in[6];
    const float* bk   = (const float*)d_in[7];
    const float* wv   = (const float*)d_in[8];
    const float* bv   = (const float*)d_in[9];
    const float* wqc  = (const float*)d_in[10];
    const float* bqc  = (const float*)d_in[11];
    const float* wkc  = (const float*)d_in[12];
    const float* bkc  = (const float*)d_in[13];
    const float* wvc  = (const float*)d_in[14];
    const float* bvc  = (const float*)d_in[15];
    const float* w_out     = (const float*)d_in[16];
    const float* b_out     = (const float*)d_in[17];
    const float* w_add_out = (const float*)d_in[18];
    const float* b_add_out = (const float*)d_in[19];
    const float* gq  = (const float*)d_in[20];
    const float* gk  = (const float*)d_in[21];
    const float* gqc = (const float*)d_in[22];
    const float* gkc = (const float*)d_in[23];
    float* out = (float*)d_out;

    __half *qj, *kj, *vj, *oj, *wr, *xr, *cr;
    cudaGetSymbolAddress((void**)&qj, g_qj);
    cudaGetSymbolAddress((void**)&kj, g_kj);
    cudaGetSymbolAddress((void**)&vj, g_vj);
    cudaGetSymbolAddress((void**)&oj, g_oj);
    cudaGetSymbolAddress((void**)&wr, g_wr);
    cudaGetSymbolAddress((void**)&xr, g_xr);
    cudaGetSymbolAddress((void**)&cr, g_cr);

    cudaFuncSetAttribute(gemm_fp16, cudaFuncAttributeMaxDynamicSharedMemorySize,
                         GEMM_SMEM_BYTES);
    cudaFuncSetAttribute(attn_kernel, cudaFuncAttributeMaxDynamicSharedMemorySize,
                         ATTN_SMEM_BYTES);

    // --- Pre-pass: round weights + activations to fp16 ---
    RoundSrc8 rs;
    rs.s[0] = wq;  rs.s[1] = wk;  rs.s[2] = wv;
    rs.s[3] = wqc; rs.s[4] = wkc; rs.s[5] = wvc;
    rs.s[6] = w_out; rs.s[7] = w_add_out;
    round_w_kernel<<<dim3(W_ELEMS / 4 / 256, 8), 256>>>(rs, wr);
    round_kernel<<<BATCH * 1024 * DIM_ / 4 / 256, 256>>>(x, xr);
    round_kernel<<<BATCH * 512 * DIM_ / 4 / 256, 256>>>(ctx, cr);

    // --- Merged QKV GEMMs (6 jobs in one launch), BN=256, BK=64 ---
    GemmJobs6 qkv;
    qkv.j[0] = { xr, wr + 0 * (size_t)W_ELEMS, bq, qj, 2048, 2048, 0, 1024, 1536, 512, 16, 0 };
    qkv.j[1] = { xr, wr + 1 * (size_t)W_ELEMS, bk, kj, 2048, 2048, 0, 1024, 1536, 512, 16, 0 };
    qkv.j[2] = { xr, wr + 2 * (size_t)W_ELEMS, bv, vj, 2048, 2048, 0, 1024, 1536, 512, 16, 0 };
    qkv.j[3] = { cr, wr + 3 * (size_t)W_ELEMS, bqc, qj, 1024, 1024, 0, 512, 1536, 0, 8, 0 };
    qkv.j[4] = { cr, wr + 4 * (size_t)W_ELEMS, bkc, kj, 1024, 1024, 0, 512, 1536, 0, 8, 0 };
    qkv.j[5] = { cr, wr + 5 * (size_t)W_ELEMS, bvc, vj, 1024, 1024, 0, 512, 1536, 0, 8, 0 };
    gemm_fp16<<<dim3(12, 16, 6), 256, GEMM_SMEM_BYTES>>>(qkv);

    // --- RMS norm + RoPE (half in/out) ---
    rms_rope_kernel<<<dim3(S_TOT, BATCH, 2), dim3(128)>>>(qj, kj, cosr, sinr, gq, gk, gqc, gkc);

    // --- Attention (fp16 operands) ---
    attn_kernel<<<dim3(S_TOT / 64, HEADS_, BATCH), 256, ATTN_SMEM_BYTES>>>(qj, kj, vj, oj);

    // --- Merged output projections (2 jobs, float output) ---
    GemmJobs6 outp;
    outp.j[0] = { oj, wr + 7 * (size_t)W_ELEMS, b_add_out, out,
                  512, 1536, 0, 1024, 1024, 0, 8, 1 };
    outp.j[1] = { oj, wr + 6 * (size_t)W_ELEMS, b_out, out + (size_t)BATCH * S_TXT_ * DIM_,
                  1024, 1536, 512, 2048, 2048, 0, 16, 1 };
    outp.j[2] = outp.j[0]; outp.j[3] = outp.j[0]; outp.j[4] = outp.j[0]; outp.j[5] = outp.j[0];
    gemm_fp16<<<dim3(12, 16, 2), 256, GEMM_SMEM_BYTES>>>(outp);
}

// round 16
// speedup vs baseline: 6.2840x; 1.0106x over previous
#include <cstdint>
#include <cuda_runtime.h>
#include <cuda_fp16.h>
#include <mma.h>

using namespace nvcuda;

#define DIM_   3072
#define S_TOT  1536
#define S_TXT_ 512
#define BATCH  2
#define HD_    128
#define HEADS_ 24
#define SCALE_ 0.08838834764831845f   // 1/sqrt(128)
#define QSCALE_ (SCALE_ * 1.4426950408889634f)   // fold log2(e) for exp2 softmax

#define JOINT_ELEMS (BATCH * S_TOT * DIM_)   // 9,437,184
#define W_ELEMS (DIM_ * DIM_)                // 9,437,184

// Scratch (no allocations allowed) — all half (same 10-bit mantissa as tf32).
__device__ __half g_qj[JOINT_ELEMS];
__device__ __half g_kj[JOINT_ELEMS];
__device__ __half g_vj[JOINT_ELEMS];
__device__ __half g_oj[JOINT_ELEMS];
__device__ __half g_wr[8 * W_ELEMS];          // fp16-rounded weights [K,N]
__device__ __half g_xr[BATCH * 1024 * DIM_];  // fp16-rounded x
__device__ __half g_cr[BATCH * 512 * DIM_];   // fp16-rounded ctx

__device__ __forceinline__ void cp_async16(void* smem_dst, const void* gmem_src) {
    unsigned int d = (unsigned int)__cvta_generic_to_shared(smem_dst);
    asm volatile("cp.async.cg.shared.global [%0], [%1], 16;\n" :: "r"(d), "l"(gmem_src));
}
#define CP_COMMIT() asm volatile("cp.async.commit_group;\n")
#define CP_WAIT(n)  asm volatile("cp.async.wait_group %0;\n" :: "n"(n))

// Packed half2 exp2 via one MUFU op (vs two for scalar fp32 EX2).
__device__ __forceinline__ unsigned int h2exp2_bits(unsigned int xbits) {
    unsigned int y;
    asm("ex2.approx.f16x2 %0, %1;" : "=r"(y) : "r"(xbits));
    return y;
}

// ---------------------------------------------------------------------------
// Pre-pass: round tensors to fp16 once.
// ---------------------------------------------------------------------------
struct RoundSrc8 { const float* s[8]; };

__global__ void __launch_bounds__(256) round_w_kernel(RoundSrc8 rs, __half* __restrict__ dst) {
    int t = blockIdx.x * 256 + threadIdx.x;            // float4 index
    int w = blockIdx.y;
    float4 v = ((const float4*)rs.s[w])[t];
    __half2* d = (__half2*)(dst + (size_t)w * W_ELEMS) + (size_t)t * 2;
    d[0] = __floats2half2_rn(v.x, v.y);
    d[1] = __floats2half2_rn(v.z, v.w);
}

__global__ void __launch_bounds__(256) round_kernel(const float* __restrict__ src,
                                                    __half* __restrict__ dst) {
    int t = blockIdx.x * 256 + threadIdx.x;
    float4 v = ((const float4*)src)[t];
    __half2* d = (__half2*)dst + (size_t)t * 2;
    d[0] = __floats2half2_rn(v.x, v.y);
    d[1] = __floats2half2_rn(v.z, v.w);
}

// ---------------------------------------------------------------------------
// FP16 GEMM: BM=128, BN=256, BK=64, 256 threads (8 warps, 2x4 warp grid,
// warp tile 64x64). 3-stage cp.async pipeline.
// Per stage (halfs): A 128x72 = 18432 B, B 64x264 = 33792 B -> 52224 B.
// 3 stages = 156672 B. Epilogue Cs 128x260 f32 = 133120 B (<= alloc).
// ---------------------------------------------------------------------------
#define GEMM_SMEM_BYTES 156672

struct GemmJob {
    const __half* A; const __half* W; const float* bias; void* C;
    int in_rpb, in_bsr, in_off;
    int out_rpb, out_bsr, out_off;
    int grid_y, out_float;
};
struct GemmJobs6 { GemmJob j[6]; };

__global__ void __launch_bounds__(256) gemm_fp16(GemmJobs6 jobs)
{
    const GemmJob jb = jobs.j[blockIdx.z];
    if ((int)blockIdx.y >= jb.grid_y) return;

    extern __shared__ char smc[];
    const __half* __restrict__ A = jb.A;
    const __half* __restrict__ W = jb.W;

    const int tid  = threadIdx.x;
    const int warp = tid >> 5;
    const int wm   = warp >> 2;     // 0..1 : row block of 64
    const int wn   = warp & 3;      // 0..3 : col block of 64
    const int m0   = blockIdx.y * 128;
    const int n0   = blockIdx.x * 256;
    const int in_base  = (m0 / jb.in_rpb) * jb.in_bsr + jb.in_off + (m0 % jb.in_rpb);
    const int out_base = (m0 / jb.out_rpb) * jb.out_bsr + jb.out_off + (m0 % jb.out_rpb);

    wmma::fragment<wmma::accumulator, 16, 16, 16, float> cf[4][4];
    #pragma unroll
    for (int i = 0; i < 4; i++)
        #pragma unroll
        for (int j = 0; j < 4; j++)
            wmma::fill_fragment(cf[i][j], 0.0f);

    #define GEMM_PREFETCH(k0, slot) do {                                          \
        __half* Ad = (__half*)(smc + (slot) * 52224);                             \
        __half* Bd = (__half*)(smc + (slot) * 52224 + 18432);                     \
        _Pragma("unroll")                                                         \
        for (int it = 0; it < 4; it++) {                                          \
            int idx = tid + it * 256;                                             \
            int r = idx >> 3, c = idx & 7;                                        \
            cp_async16(&Ad[r * 72 + c * 8],                                       \
                       &A[(size_t)(in_base + r) * DIM_ + (k0) + c * 8]);          \
        }                                                                         \
        _Pragma("unroll")                                                         \
        for (int it = 0; it < 8; it++) {                                          \
            int idx = tid + it * 256;                                             \
            int r = idx >> 5, c = idx & 31;                                       \
            cp_async16(&Bd[r * 264 + c * 8],                                      \
                       &W[(size_t)((k0) + r) * DIM_ + n0 + c * 8]);               \
        }                                                                         \
    } while (0)

    #pragma unroll
    for (int s = 0; s < 3; s++) { GEMM_PREFETCH(s * 64, s); CP_COMMIT(); }

    const int NSTAGE = DIM_ / 64;   // 48
    for (int i = 0; i < NSTAGE; i++) {
        CP_WAIT(2);
        __syncthreads();

        int slot = i % 3;
        __half* Ab = (__half*)(smc + slot * 52224);
        __half* Bb = (__half*)(smc + slot * 52224 + 18432);

        #pragma unroll
        for (int kk = 0; kk < 64; kk += 16) {
            wmma::fragment<wmma::matrix_a, 16, 16, 16, __half, wmma::row_major> af[4];
            wmma::fragment<wmma::matrix_b, 16, 16, 16, __half, wmma::row_major> bf[4];
            #pragma unroll
            for (int ii = 0; ii < 4; ii++)
                wmma::load_matrix_sync(af[ii], &Ab[(wm * 64 + ii * 16) * 72 + kk], 72);
            #pragma unroll
            for (int jj = 0; jj < 4; jj++)
                wmma::load_matrix_sync(bf[jj], &Bb[kk * 264 + wn * 64 + jj * 16], 264);
            #pragma unroll
            for (int ii = 0; ii < 4; ii++)
                #pragma unroll
                for (int jj = 0; jj < 4; jj++)
                    wmma::mma_sync(cf[ii][jj], af[ii], bf[jj], cf[ii][jj]);
        }
        __syncthreads();

        if (i + 3 < NSTAGE) GEMM_PREFETCH((i + 3) * 64, slot);
        CP_COMMIT();
    }

    // Epilogue: stage through smem (fp32), add bias, store half or float.
    float* Cs = (float*)smc;   // 128 x 260
    #pragma unroll
    for (int i = 0; i < 4; i++)
        #pragma unroll
        for (int j = 0; j < 4; j++)
            wmma::store_matrix_sync(&Cs[(wm * 64 + i * 16) * 260 + wn * 64 + j * 16],
                                    cf[i][j], 260, wmma::mem_row_major);
    __syncthreads();

    #pragma unroll
    for (int it = 0; it < 32; it++) {
        int idx4 = tid + it * 256;
        int r = idx4 >> 6, c4 = idx4 & 63;
        float4 v  = *(float4*)&Cs[r * 260 + c4 * 4];
        float4 bb = *(const float4*)&jb.bias[n0 + c4 * 4];
        v.x += bb.x; v.y += bb.y; v.z += bb.z; v.w += bb.w;
        size_t off = (size_t)(out_base + r) * DIM_ + n0 + c4 * 4;
        if (jb.out_float) {
            *(float4*)((float*)jb.C + off) = v;
        } else {
            __half2 h0 = __floats2half2_rn(v.x, v.y);
            __half2 h1 = __floats2half2_rn(v.z, v.w);
            __half2* dst = (__half2*)((__half*)jb.C + off);
            dst[0] = h0; dst[1] = h1;
        }
    }
}

// ---------------------------------------------------------------------------
// Fused RMSNorm + RoPE, in-place on joint half Q (z=0) and K (z=1).
// ---------------------------------------------------------------------------
__global__ void __launch_bounds__(128) rms_rope_kernel(
    __half* __restrict__ q, __half* __restrict__ k,
    const float* __restrict__ cosr, const float* __restrict__ sinr,
    const float* __restrict__ gq, const float* __restrict__ gk,
    const float* __restrict__ gqc, const float* __restrict__ gkc)
{
    const int j = blockIdx.x, b = blockIdx.y, which = blockIdx.z;
    __half* buf = which ? k : q;
    const float* g = which ? (j < S_TXT_ ? gkc : gk)
                           : (j < S_TXT_ ? gqc : gq);
    const int lane = threadIdx.x & 31;
    const int warp = threadIdx.x >> 5;
    const size_t rowbase = ((size_t)(b * S_TOT + j)) * DIM_;

    const float c0 = cosr[j * 64 + lane];
    const float s0 = sinr[j * 64 + lane];
    const float c1 = cosr[j * 64 + lane + 32];
    const float s1 = sinr[j * 64 + lane + 32];

    for (int h = warp; h < HEADS_; h += 4) {
        __half* p = buf + rowbase + h * HD_;
        float2 e0 = __half22float2(*(__half2*)&p[2 * lane]);
        float2 e1 = __half22float2(*(__half2*)&p[2 * (lane + 32)]);
        float ss = e0.x * e0.x + e0.y * e0.y + e1.x * e1.x + e1.y * e1.y;
        #pragma unroll
        for (int o = 16; o; o >>= 1) ss += __shfl_xor_sync(0xffffffffu, ss, o);
        float inv = rsqrtf(ss * (1.0f / 128.0f) + 1e-6f);

        float x1 = e0.x * inv * g[2 * lane];
        float x2 = e0.y * inv * g[2 * lane + 1];
        float y1 = e1.x * inv * g[2 * (lane + 32)];
        float y2 = e1.y * inv * g[2 * (lane + 32) + 1];

        *(__half2*)&p[2 * lane] =
            __floats2half2_rn(x1 * c0 - x2 * s0, x1 * s0 + x2 * c0);
        *(__half2*)&p[2 * (lane + 32)] =
            __floats2half2_rn(y1 * c1 - y2 * s1, y1 * s1 + y2 * c1);
    }
}

// ---------------------------------------------------------------------------
// Flash-style attention (fp16 operands, fp32 max/sum, half2 EX2 softmax).
// smem layout (bytes):
//   Ksh  half 128x136 : [0, 34816)
//   Vsh  half 128x136 : [34816, 69632)
//   Psh  half  64x136 : [69632, 87040)   (Q staging, then P)
//   Ss   f32   64x132 : [87040, 120832)  (scores)
//   Os   f32   64x132 : [120832, 154624)
//   mrow/lrow f32 64+64: [154624, 155136)
// ---------------------------------------------------------------------------
#define ATTN_SMEM_BYTES 155136

__global__ void __launch_bounds__(256) attn_kernel(
    const __half* __restrict__ qj, const __half* __restrict__ kj,
    const __half* __restrict__ vj, __half* __restrict__ oj)
{
    extern __shared__ char smc[];
    __half* Ksh = (__half*)smc;                   // ld 136
    __half* Vsh = (__half*)(smc + 34816);         // ld 136
    __half* Psh = (__half*)(smc + 69632);         // ld 136
    float*  Ss  = (float*)(smc + 87040);          // ld 132
    float*  Os  = (float*)(smc + 120832);         // ld 132
    float*  mrow = (float*)(smc + 154624);        // 64
    float*  lrow = (float*)(smc + 154624 + 256);  // 64

    const int tid  = threadIdx.x;
    const int warp = tid >> 5;
    const int wm   = warp >> 1;       // 0..3 : 16-row block
    const int wn   = warp & 1;        // 0..1 : 64-col block
    const int q0   = blockIdx.x * 64;
    const int h    = blockIdx.y;
    const int b    = blockIdx.z;
    const size_t hd0 = (size_t)h * HD_;

    #define ATTN_LOAD_K(kt) do {                                                  \
        _Pragma("unroll")                                                         \
        for (int it = 0; it < 8; it++) {                                          \
            int idx = tid + it * 256;                                             \
            int r = idx >> 4, c = idx & 15;                                       \
            size_t gaddr = ((size_t)(b * S_TOT + (kt) + r)) * DIM_ + hd0 + c * 8; \
            cp_async16(&Ksh[r * 136 + c * 8], &kj[gaddr]);                        \
        }                                                                         \
    } while (0)
    #define ATTN_LOAD_V(kt) do {                                                  \
        _Pragma("unroll")                                                         \
        for (int it = 0; it < 8; it++) {                                          \
            int idx = tid + it * 256;                                             \
            int r = idx >> 4, c = idx & 15;                                       \
            size_t gaddr = ((size_t)(b * S_TOT + (kt) + r)) * DIM_ + hd0 + c * 8; \
            cp_async16(&Vsh[r * 136 + c * 8], &vj[gaddr]);                        \
        }                                                                         \
    } while (0)

    // Prologue: start K0 / V0 transfers, then stage Q while they fly.
    ATTN_LOAD_K(0); CP_COMMIT();
    ATTN_LOAD_V(0); CP_COMMIT();

    // Q staging (half, scaled by QSCALE): 64 rows x 64 half2, 16/thread.
    #pragma unroll
    for (int it = 0; it < 16; it++) {
        int idx = tid + it * 256;
        int r = idx >> 6, c2 = idx & 63;
        size_t gaddr = ((size_t)(b * S_TOT + q0 + r)) * DIM_ + hd0 + c2 * 2;
        float2 v = __half22float2(*(const __half2*)&qj[gaddr]);
        *(__half2*)&Psh[r * 136 + c2 * 2] =
            __floats2half2_rn(v.x * QSCALE_, v.y * QSCALE_);
    }
    // Init O and stats.
    #pragma unroll
    for (int it = 0; it < 8; it++) {
        int idx4 = tid + it * 256;
        int r = idx4 >> 5, c4 = idx4 & 31;
        *(float4*)&Os[r * 132 + c4 * 4] = make_float4(0.f, 0.f, 0.f, 0.f);
    }
    if (tid < 64) { mrow[tid] = -1e30f; lrow[tid] = 0.f; }
    __syncthreads();

    // Preload Q fragments for this warp's 16 rows (8 k-chunks of 16).
    wmma::fragment<wmma::matrix_a, 16, 16, 16, __half, wmma::row_major> qf[8];
    #pragma unroll
    for (int t = 0; t < 8; t++)
        wmma::load_matrix_sync(qf[t], &Psh[(wm * 16) * 136 + t * 16], 136);
    __syncthreads();  // Psh reused for P

    const int r_sm = tid >> 2;
    const int sub  = tid & 3;

    for (int kt = 0; kt < S_TOT; kt += 128) {
        const bool have_next = (kt + 128 < S_TOT);

        // K_i ready (V_i may still be in flight).
        CP_WAIT(1);
        __syncthreads();

        // Scores -> Ss (fp32).
        #pragma unroll
        for (int n = 0; n < 4; n++) {
            wmma::fragment<wmma::accumulator, 16, 16, 16, float> cfr;
            wmma::fill_fragment(cfr, 0.0f);
            #pragma unroll
            for (int kk = 0; kk < 8; kk++) {
                wmma::fragment<wmma::matrix_b, 16, 16, 16, __half, wmma::col_major> bf;
                wmma::load_matrix_sync(bf, &Ksh[(wn * 64 + n * 16) * 136 + kk * 16], 136);
                wmma::mma_sync(cfr, qf[kk], bf, cfr);
            }
            wmma::store_matrix_sync(&Ss[(wm * 16) * 132 + wn * 64 + n * 16],
                                    cfr, 132, wmma::mem_row_major);
        }
        __syncthreads();     // Ksh fully consumed

        // Prefetch next K while softmax runs.
        if (have_next) { ATTN_LOAD_K(kt + 128); CP_COMMIT(); }

        // Online softmax (log2 domain), half2 EX2: one MUFU per 2 values.
        // P (half) is the exact value used in PV; l sums those same halfs,
        // so numerator/denominator errors cancel in O/l.
        {
            float* srow = &Ss[r_sm * 132 + sub * 32];
            float mx = -1e30f;
            float4 vv[8];
            #pragma unroll
            for (int i = 0; i < 8; i++) {
                vv[i] = ((float4*)srow)[i];
                mx = fmaxf(mx, fmaxf(fmaxf(vv[i].x, vv[i].y), fmaxf(vv[i].z, vv[i].w)));
            }
            mx = fmaxf(mx, __shfl_xor_sync(0xffffffffu, mx, 1));
            mx = fmaxf(mx, __shfl_xor_sync(0xffffffffu, mx, 2));
            float mold = mrow[r_sm];
            float newm = fmaxf(mold, mx);
            float f = exp2f(mold - newm);
            float sum = 0.f;
            unsigned int* prow = (unsigned int*)&Psh[r_sm * 136 + sub * 32];
            #pragma unroll
            for (int i = 0; i < 8; i++) {
                __half2 a0 = __floats2half2_rn(vv[i].x - newm, vv[i].y - newm);
                __half2 a1 = __floats2half2_rn(vv[i].z - newm, vv[i].w - newm);
                unsigned int p0 = h2exp2_bits(*(unsigned int*)&a0);
                unsigned int p1 = h2exp2_bits(*(unsigned int*)&a1);
                prow[2 * i]     = p0;
                prow[2 * i + 1] = p1;
                float2 f0 = __half22float2(*(__half2*)&p0);
                float2 f1 = __half22float2(*(__half2*)&p1);
                sum += (f0.x + f0.y) + (f1.x + f1.y);
            }
            sum += __shfl_xor_sync(0xffffffffu, sum, 1);
            sum += __shfl_xor_sync(0xffffffffu, sum, 2);
            if (sub == 0) { lrow[r_sm] = lrow[r_sm] * f + sum; mrow[r_sm] = newm; }
            // Rescale O only when the running max actually changed.
            if (f != 1.0f) {
                float* orow = &Os[r_sm * 132 + sub * 32];
                #pragma unroll
                for (int i = 0; i < 8; i++) {
                    float4 o = ((float4*)orow)[i];
                    o.x *= f; o.y *= f; o.z *= f; o.w *= f;
                    ((float4*)orow)[i] = o;
                }
            }
        }

        // V_i ready.
        if (have_next) { CP_WAIT(1); } else { CP_WAIT(0); }
        __syncthreads();

        // PV: O += P @ V.
        wmma::fragment<wmma::matrix_a, 16, 16, 16, __half, wmma::row_major> pf[8];
        #pragma unroll
        for (int kk = 0; kk < 8; kk++)
            wmma::load_matrix_sync(pf[kk], &Psh[(wm * 16) * 136 + kk * 16], 136);
        #pragma unroll
        for (int n = 0; n < 4; n++) {
            wmma::fragment<wmma::accumulator, 16, 16, 16, float> cfr;
            wmma::load_matrix_sync(cfr, &Os[(wm * 16) * 132 + wn * 64 + n * 16],
                                   132, wmma::mem_row_major);
            #pragma unroll
            for (int kk = 0; kk < 8; kk++) {
                wmma::fragment<wmma::matrix_b, 16, 16, 16, __half, wmma::row_major> bf;
                wmma::load_matrix_sync(bf, &Vsh[(kk * 16) * 136 + wn * 64 + n * 16], 136);
                wmma::mma_sync(cfr, pf[kk], bf, cfr);
            }
            wmma::store_matrix_sync(&Os[(wm * 16) * 132 + wn * 64 + n * 16],
                                    cfr, 132, wmma::mem_row_major);
        }
        __syncthreads();     // Vsh fully consumed

        // Prefetch next V.
        if (have_next) { ATTN_LOAD_V(kt + 128); CP_COMMIT(); }
    }

    // Writeout: O / l -> half oj.
    #pragma unroll
    for (int it = 0; it < 8; it++) {
        int idx4 = tid + it * 256;
        int r = idx4 >> 5, c4 = idx4 & 31;
        float inv = 1.0f / lrow[r];
        float4 v = *(float4*)&Os[r * 132 + c4 * 4];
        size_t gaddr = ((size_t)(b * S_TOT + q0 + r)) * DIM_ + hd0 + c4 * 4;
        __half2* dst = (__half2*)&oj[gaddr];
        dst[0] = __floats2half2_rn(v.x * inv, v.y * inv);
        dst[1] = __floats2half2_rn(v.z * inv, v.w * inv);
    }
}

// ---------------------------------------------------------------------------
extern "C" void kernel_launch(void* const* d_in, const int* in_sizes, int n_in,
                              void* d_out, int out_size)
{
    const float* x    = (const float*)d_in[0];
    const float* ctx  = (const float*)d_in[1];
    const float* cosr = (const float*)d_in[2];
    const float* sinr = (const float*)d_in[3];
    const float* wq   = (const float*)d_in[4];
    const float* bq   = (const float*)d_in[5];
    const float* wk   = (const float*)d_in[6];
    const float* bk   = (const float*)d_in[7];
    const float* wv   = (const float*)d_in[8];
    const float* bv   = (const float*)d_in[9];
    const float* wqc  = (const float*)d_in[10];
    const float* bqc  = (const float*)d_in[11];
    const float* wkc  = (const float*)d_in[12];
    const float* bkc  = (const float*)d_in[13];
    const float* wvc  = (const float*)d_in[14];
    const float* bvc  = (const float*)d_in[15];
    const float* w_out     = (const float*)d_in[16];
    const float* b_out     = (const float*)d_in[17];
    const float* w_add_out = (const float*)d_in[18];
    const float* b_add_out = (const float*)d_in[19];
    const float* gq  = (const float*)d_in[20];
    const float* gk  = (const float*)d_in[21];
    const float* gqc = (const float*)d_in[22];
    const float* gkc = (const float*)d_in[23];
    float* out = (float*)d_out;

    __half *qj, *kj, *vj, *oj, *wr, *xr, *cr;
    cudaGetSymbolAddress((void**)&qj, g_qj);
    cudaGetSymbolAddress((void**)&kj, g_kj);
    cudaGetSymbolAddress((void**)&vj, g_vj);
    cudaGetSymbolAddress((void**)&oj, g_oj);
    cudaGetSymbolAddress((void**)&wr, g_wr);
    cudaGetSymbolAddress((void**)&xr, g_xr);
    cudaGetSymbolAddress((void**)&cr, g_cr);

    cudaFuncSetAttribute(gemm_fp16, cudaFuncAttributeMaxDynamicSharedMemorySize,
                         GEMM_SMEM_BYTES);
    cudaFuncSetAttribute(attn_kernel, cudaFuncAttributeMaxDynamicSharedMemorySize,
                         ATTN_SMEM_BYTES);

    // --- Pre-pass: round weights + activations to fp16 ---
    RoundSrc8 rs;
    rs.s[0] = wq;  rs.s[1] = wk;  rs.s[2] = wv;
    rs.s[3] = wqc; rs.s[4] = wkc; rs.s[5] = wvc;
    rs.s[6] = w_out; rs.s[7] = w_add_out;
    round_w_kernel<<<dim3(W_ELEMS / 4 / 256, 8), 256>>>(rs, wr);
    round_kernel<<<BATCH * 1024 * DIM_ / 4 / 256, 256>>>(x, xr);
    round_kernel<<<BATCH * 512 * DIM_ / 4 / 256, 256>>>(ctx, cr);

    // --- Merged QKV GEMMs (6 jobs in one launch), BN=256, BK=64 ---
    GemmJobs6 qkv;
    qkv.j[0] = { xr, wr + 0 * (size_t)W_ELEMS, bq, qj, 2048, 2048, 0, 1024, 1536, 512, 16, 0 };
    qkv.j[1] = { xr, wr + 1 * (size_t)W_ELEMS, bk, kj, 2048, 2048, 0, 1024, 1536, 512, 16, 0 };
    qkv.j[2] = { xr, wr + 2 * (size_t)W_ELEMS, bv, vj, 2048, 2048, 0, 1024, 1536, 512, 16, 0 };
    qkv.j[3] = { cr, wr + 3 * (size_t)W_ELEMS, bqc, qj, 1024, 1024, 0, 512, 1536, 0, 8, 0 };
    qkv.j[4] = { cr, wr + 4 * (size_t)W_ELEMS, bkc, kj, 1024, 1024, 0, 512, 1536, 0, 8, 0 };
    qkv.j[5] = { cr, wr + 5 * (size_t)W_ELEMS, bvc, vj, 1024, 1024, 0, 512, 1536, 0, 8, 0 };
    gemm_fp16<<<dim3(12, 16, 6), 256, GEMM_SMEM_BYTES>>>(qkv);

    // --- RMS norm + RoPE (half in/out) ---
    rms_rope_kernel<<<dim3(S_TOT, BATCH, 2), dim3(128)>>>(qj, kj, cosr, sinr, gq, gk, gqc, gkc);

    // --- Attention (fp16 operands, half2 EX2 softmax) ---
    attn_kernel<<<dim3(S_TOT / 64, HEADS_, BATCH), 256, ATTN_SMEM_BYTES>>>(qj, kj, vj, oj);

    // --- Merged output projections (2 jobs, float output) ---
    GemmJobs6 outp;
    outp.j[0] = { oj, wr + 7 * (size_t)W_ELEMS, b_add_out, out,
                  512, 1536, 0, 1024, 1024, 0, 8, 1 };
    outp.j[1] = { oj, wr + 6 * (size_t)W_ELEMS, b_out, out + (size_t)BATCH * S_TXT_ * DIM_,
                  1024, 1536, 512, 2048, 2048, 0, 16, 1 };
    outp.j[2] = outp.j[0]; outp.j[3] = outp.j[0]; outp.j[4] = outp.j[0]; outp.j[5] = outp.j[0];
    gemm_fp16<<<dim3(12, 16, 2), 256, GEMM_SMEM_BYTES>>>(outp);
}

// round 17
// speedup vs baseline: 6.3712x; 1.0139x over previous
#include <cstdint>
#include <cuda_runtime.h>
#include <cuda_fp16.h>
#include <mma.h>

using namespace nvcuda;

#define DIM_   3072
#define S_TOT  1536
#define S_TXT_ 512
#define BATCH  2
#define HD_    128
#define HEADS_ 24
#define SCALE_ 0.08838834764831845f   // 1/sqrt(128)
#define QSCALE_ (SCALE_ * 1.4426950408889634f)   // fold log2(e) for exp2 softmax

#define JOINT_ELEMS (BATCH * S_TOT * DIM_)   // 9,437,184
#define W_ELEMS (DIM_ * DIM_)                // 9,437,184

// Scratch (no allocations allowed) — all half.
__device__ __half g_qj[JOINT_ELEMS];
__device__ __half g_kj[JOINT_ELEMS];
__device__ __half g_vj[JOINT_ELEMS];
__device__ __half g_oj[JOINT_ELEMS];
__device__ __half g_wr[8 * W_ELEMS];          // fp16-rounded weights [K,N]
__device__ __half g_xr[BATCH * 1024 * DIM_];  // fp16-rounded x
__device__ __half g_cr[BATCH * 512 * DIM_];   // fp16-rounded ctx

__device__ __forceinline__ void cp_async16(void* smem_dst, const void* gmem_src) {
    unsigned int d = (unsigned int)__cvta_generic_to_shared(smem_dst);
    asm volatile("cp.async.cg.shared.global [%0], [%1], 16;\n" :: "r"(d), "l"(gmem_src));
}
#define CP_COMMIT() asm volatile("cp.async.commit_group;\n")
#define CP_WAIT(n)  asm volatile("cp.async.wait_group %0;\n" :: "n"(n))

// Packed half2 exp2 via one MUFU op.
__device__ __forceinline__ unsigned int h2exp2_bits(unsigned int xbits) {
    unsigned int y;
    asm("ex2.approx.f16x2 %0, %1;" : "=r"(y) : "r"(xbits));
    return y;
}

// ---------------------------------------------------------------------------
// Pre-pass: round tensors to fp16 once.
// ---------------------------------------------------------------------------
struct RoundSrc8 { const float* s[8]; };

__global__ void __launch_bounds__(256) round_w_kernel(RoundSrc8 rs, __half* __restrict__ dst) {
    int t = blockIdx.x * 256 + threadIdx.x;            // float4 index
    int w = blockIdx.y;
    float4 v = ((const float4*)rs.s[w])[t];
    __half2* d = (__half2*)(dst + (size_t)w * W_ELEMS) + (size_t)t * 2;
    d[0] = __floats2half2_rn(v.x, v.y);
    d[1] = __floats2half2_rn(v.z, v.w);
}

__global__ void __launch_bounds__(256) round_kernel(const float* __restrict__ src,
                                                    __half* __restrict__ dst) {
    int t = blockIdx.x * 256 + threadIdx.x;
    float4 v = ((const float4*)src)[t];
    __half2* d = (__half2*)dst + (size_t)t * 2;
    d[0] = __floats2half2_rn(v.x, v.y);
    d[1] = __floats2half2_rn(v.z, v.w);
}

// ---------------------------------------------------------------------------
// FP16 GEMM (unchanged, passing): BM=128, BN=256, BK=64, 256 threads,
// 3-stage cp.async pipeline.
// ---------------------------------------------------------------------------
#define GEMM_SMEM_BYTES 156672

struct GemmJob {
    const __half* A; const __half* W; const float* bias; void* C;
    int in_rpb, in_bsr, in_off;
    int out_rpb, out_bsr, out_off;
    int grid_y, out_float;
};
struct GemmJobs6 { GemmJob j[6]; };

__global__ void __launch_bounds__(256) gemm_fp16(GemmJobs6 jobs)
{
    const GemmJob jb = jobs.j[blockIdx.z];
    if ((int)blockIdx.y >= jb.grid_y) return;

    extern __shared__ char smc[];
    const __half* __restrict__ A = jb.A;
    const __half* __restrict__ W = jb.W;

    const int tid  = threadIdx.x;
    const int warp = tid >> 5;
    const int wm   = warp >> 2;
    const int wn   = warp & 3;
    const int m0   = blockIdx.y * 128;
    const int n0   = blockIdx.x * 256;
    const int in_base  = (m0 / jb.in_rpb) * jb.in_bsr + jb.in_off + (m0 % jb.in_rpb);
    const int out_base = (m0 / jb.out_rpb) * jb.out_bsr + jb.out_off + (m0 % jb.out_rpb);

    wmma::fragment<wmma::accumulator, 16, 16, 16, float> cf[4][4];
    #pragma unroll
    for (int i = 0; i < 4; i++)
        #pragma unroll
        for (int j = 0; j < 4; j++)
            wmma::fill_fragment(cf[i][j], 0.0f);

    #define GEMM_PREFETCH(k0, slot) do {                                          \
        __half* Ad = (__half*)(smc + (slot) * 52224);                             \
        __half* Bd = (__half*)(smc + (slot) * 52224 + 18432);                     \
        _Pragma("unroll")                                                         \
        for (int it = 0; it < 4; it++) {                                          \
            int idx = tid + it * 256;                                             \
            int r = idx >> 3, c = idx & 7;                                        \
            cp_async16(&Ad[r * 72 + c * 8],                                       \
                       &A[(size_t)(in_base + r) * DIM_ + (k0) + c * 8]);          \
        }                                                                         \
        _Pragma("unroll")                                                         \
        for (int it = 0; it < 8; it++) {                                          \
            int idx = tid + it * 256;                                             \
            int r = idx >> 5, c = idx & 31;                                       \
            cp_async16(&Bd[r * 264 + c * 8],                                      \
                       &W[(size_t)((k0) + r) * DIM_ + n0 + c * 8]);               \
        }                                                                         \
    } while (0)

    #pragma unroll
    for (int s = 0; s < 3; s++) { GEMM_PREFETCH(s * 64, s); CP_COMMIT(); }

    const int NSTAGE = DIM_ / 64;   // 48
    for (int i = 0; i < NSTAGE; i++) {
        CP_WAIT(2);
        __syncthreads();

        int slot = i % 3;
        __half* Ab = (__half*)(smc + slot * 52224);
        __half* Bb = (__half*)(smc + slot * 52224 + 18432);

        #pragma unroll
        for (int kk = 0; kk < 64; kk += 16) {
            wmma::fragment<wmma::matrix_a, 16, 16, 16, __half, wmma::row_major> af[4];
            wmma::fragment<wmma::matrix_b, 16, 16, 16, __half, wmma::row_major> bf[4];
            #pragma unroll
            for (int ii = 0; ii < 4; ii++)
                wmma::load_matrix_sync(af[ii], &Ab[(wm * 64 + ii * 16) * 72 + kk], 72);
            #pragma unroll
            for (int jj = 0; jj < 4; jj++)
                wmma::load_matrix_sync(bf[jj], &Bb[kk * 264 + wn * 64 + jj * 16], 264);
            #pragma unroll
            for (int ii = 0; ii < 4; ii++)
                #pragma unroll
                for (int jj = 0; jj < 4; jj++)
                    wmma::mma_sync(cf[ii][jj], af[ii], bf[jj], cf[ii][jj]);
        }
        __syncthreads();

        if (i + 3 < NSTAGE) GEMM_PREFETCH((i + 3) * 64, slot);
        CP_COMMIT();
    }

    float* Cs = (float*)smc;   // 128 x 260
    #pragma unroll
    for (int i = 0; i < 4; i++)
        #pragma unroll
        for (int j = 0; j < 4; j++)
            wmma::store_matrix_sync(&Cs[(wm * 64 + i * 16) * 260 + wn * 64 + j * 16],
                                    cf[i][j], 260, wmma::mem_row_major);
    __syncthreads();

    #pragma unroll
    for (int it = 0; it < 32; it++) {
        int idx4 = tid + it * 256;
        int r = idx4 >> 6, c4 = idx4 & 63;
        float4 v  = *(float4*)&Cs[r * 260 + c4 * 4];
        float4 bb = *(const float4*)&jb.bias[n0 + c4 * 4];
        v.x += bb.x; v.y += bb.y; v.z += bb.z; v.w += bb.w;
        size_t off = (size_t)(out_base + r) * DIM_ + n0 + c4 * 4;
        if (jb.out_float) {
            *(float4*)((float*)jb.C + off) = v;
        } else {
            __half2 h0 = __floats2half2_rn(v.x, v.y);
            __half2 h1 = __floats2half2_rn(v.z, v.w);
            __half2* dst = (__half2*)((__half*)jb.C + off);
            dst[0] = h0; dst[1] = h1;
        }
    }
}

// ---------------------------------------------------------------------------
// Fused RMSNorm + RoPE (unchanged, passing).
// ---------------------------------------------------------------------------
__global__ void __launch_bounds__(128) rms_rope_kernel(
    __half* __restrict__ q, __half* __restrict__ k,
    const float* __restrict__ cosr, const float* __restrict__ sinr,
    const float* __restrict__ gq, const float* __restrict__ gk,
    const float* __restrict__ gqc, const float* __restrict__ gkc)
{
    const int j = blockIdx.x, b = blockIdx.y, which = blockIdx.z;
    __half* buf = which ? k : q;
    const float* g = which ? (j < S_TXT_ ? gkc : gk)
                           : (j < S_TXT_ ? gqc : gq);
    const int lane = threadIdx.x & 31;
    const int warp = threadIdx.x >> 5;
    const size_t rowbase = ((size_t)(b * S_TOT + j)) * DIM_;

    const float c0 = cosr[j * 64 + lane];
    const float s0 = sinr[j * 64 + lane];
    const float c1 = cosr[j * 64 + lane + 32];
    const float s1 = sinr[j * 64 + lane + 32];

    for (int h = warp; h < HEADS_; h += 4) {
        __half* p = buf + rowbase + h * HD_;
        float2 e0 = __half22float2(*(__half2*)&p[2 * lane]);
        float2 e1 = __half22float2(*(__half2*)&p[2 * (lane + 32)]);
        float ss = e0.x * e0.x + e0.y * e0.y + e1.x * e1.x + e1.y * e1.y;
        #pragma unroll
        for (int o = 16; o; o >>= 1) ss += __shfl_xor_sync(0xffffffffu, ss, o);
        float inv = rsqrtf(ss * (1.0f / 128.0f) + 1e-6f);

        float x1 = e0.x * inv * g[2 * lane];
        float x2 = e0.y * inv * g[2 * lane + 1];
        float y1 = e1.x * inv * g[2 * (lane + 32)];
        float y2 = e1.y * inv * g[2 * (lane + 32) + 1];

        *(__half2*)&p[2 * lane] =
            __floats2half2_rn(x1 * c0 - x2 * s0, x1 * s0 + x2 * c0);
        *(__half2*)&p[2 * (lane + 32)] =
            __floats2half2_rn(y1 * c1 - y2 * s1, y1 * s1 + y2 * c1);
    }
}

// ---------------------------------------------------------------------------
// Flash attention v6: 128 threads / 4 warps, WARP-LOCAL tiles.
// Warp w owns q-rows [w*16, w*16+16) for scores, softmax, P, PV, O — no
// cross-warp data flow inside a tile. K and V double-buffered: prefetch
// targets the idle buffer, so only 2 __syncthreads per tile (cp.async
// visibility after each wait).
// smem (bytes):
//   Ksh[2] half 128x136 : [0, 69632)
//   Vsh[2] half 128x136 : [69632, 139264)
//   Psh    half  64x136 : [139264, 156672)   (Q staging, then P)
//   Ss     f32   64x132 : [156672, 190464)
//   Os     f32   64x132 : [190464, 224256)
//   mrow/lrow           : [224256, 224768)
// ---------------------------------------------------------------------------
#define ATTN_SMEM_BYTES 224768

__global__ void __launch_bounds__(128) attn_kernel(
    const __half* __restrict__ qj, const __half* __restrict__ kj,
    const __half* __restrict__ vj, __half* __restrict__ oj)
{
    extern __shared__ char smc[];
    __half* Psh = (__half*)(smc + 139264);        // ld 136
    float*  Ss  = (float*)(smc + 156672);         // ld 132
    float*  Os  = (float*)(smc + 190464);         // ld 132
    float*  mrow = (float*)(smc + 224256);        // 64
    float*  lrow = (float*)(smc + 224256 + 256);  // 64

    const int tid  = threadIdx.x;
    const int warp = tid >> 5;
    const int lane = tid & 31;
    const int q0   = blockIdx.x * 64;
    const int h    = blockIdx.y;
    const int b    = blockIdx.z;
    const size_t hd0 = (size_t)h * HD_;

    // K/V tile load: 128 rows x 128 halfs = 2048 16B chunks, 128 threads -> 16 iters.
    #define ATTN_LOAD_K(kt, bufi) do {                                            \
        __half* Kd = (__half*)(smc + (bufi) * 34816);                             \
        _Pragma("unroll")                                                         \
        for (int it = 0; it < 16; it++) {                                         \
            int idx = tid + it * 128;                                             \
            int r = idx >> 4, c = idx & 15;                                       \
            size_t gaddr = ((size_t)(b * S_TOT + (kt) + r)) * DIM_ + hd0 + c * 8; \
            cp_async16(&Kd[r * 136 + c * 8], &kj[gaddr]);                         \
        }                                                                         \
    } while (0)
    #define ATTN_LOAD_V(kt, bufi) do {                                            \
        __half* Vd = (__half*)(smc + 69632 + (bufi) * 34816);                     \
        _Pragma("unroll")                                                         \
        for (int it = 0; it < 16; it++) {                                         \
            int idx = tid + it * 128;                                             \
            int r = idx >> 4, c = idx & 15;                                       \
            size_t gaddr = ((size_t)(b * S_TOT + (kt) + r)) * DIM_ + hd0 + c * 8; \
            cp_async16(&Vd[r * 136 + c * 8], &vj[gaddr]);                         \
        }                                                                         \
    } while (0)

    // Prologue: K0 -> buf0, V0 -> buf0; stage Q while they fly.
    ATTN_LOAD_K(0, 0); CP_COMMIT();
    ATTN_LOAD_V(0, 0); CP_COMMIT();

    // Q staging (half, scaled by QSCALE): 64 rows x 64 half2, 128 thr -> 32 iters.
    #pragma unroll
    for (int it = 0; it < 32; it++) {
        int idx = tid + it * 128;
        int r = idx >> 6, c2 = idx & 63;
        size_t gaddr = ((size_t)(b * S_TOT + q0 + r)) * DIM_ + hd0 + c2 * 2;
        float2 v = __half22float2(*(const __half2*)&qj[gaddr]);
        *(__half2*)&Psh[r * 136 + c2 * 2] =
            __floats2half2_rn(v.x * QSCALE_, v.y * QSCALE_);
    }
    // Init O (64x128 f32) and stats.
    #pragma unroll
    for (int it = 0; it < 16; it++) {
        int idx4 = tid + it * 128;
        int r = idx4 >> 5, c4 = idx4 & 31;
        *(float4*)&Os[r * 132 + c4 * 4] = make_float4(0.f, 0.f, 0.f, 0.f);
    }
    if (tid < 64) { mrow[tid] = -1e30f; lrow[tid] = 0.f; }
    __syncthreads();

    // Preload Q fragments for this warp's 16 rows (8 d-chunks of 16).
    wmma::fragment<wmma::matrix_a, 16, 16, 16, __half, wmma::row_major> qf[8];
    #pragma unroll
    for (int t = 0; t < 8; t++)
        wmma::load_matrix_sync(qf[t], &Psh[(warp * 16) * 136 + t * 16], 136);
    __syncthreads();  // Psh reused for P

    const int r_sm  = warp * 16 + (lane >> 1);   // this lane's softmax row
    const int chalf = lane & 1;                  // which 64-col half

    for (int kt = 0; kt < S_TOT; kt += 128) {
        const int  i = kt >> 7;
        const int  bufi = i & 1;
        const bool have_next = (kt + 128 < S_TOT);
        __half* Kb = (__half*)(smc + bufi * 34816);
        __half* Vb = (__half*)(smc + 69632 + bufi * 34816);

        // K(i) ready.
        CP_WAIT(1);
        __syncthreads();

        // Scores: warp-local 16 rows x 128 cols. k-outer / n-inner:
        // 8 independent accumulators keep the HMMA pipe streaming.
        {
            wmma::fragment<wmma::accumulator, 16, 16, 16, float> sacc[8];
            #pragma unroll
            for (int n = 0; n < 8; n++) wmma::fill_fragment(sacc[n], 0.0f);
            #pragma unroll
            for (int t = 0; t < 8; t++) {
                #pragma unroll
                for (int n = 0; n < 8; n++) {
                    wmma::fragment<wmma::matrix_b, 16, 16, 16, __half, wmma::col_major> bf;
                    wmma::load_matrix_sync(bf, &Kb[(n * 16) * 136 + t * 16], 136);
                    wmma::mma_sync(sacc[n], qf[t], bf, sacc[n]);
                }
            }
            #pragma unroll
            for (int n = 0; n < 8; n++)
                wmma::store_matrix_sync(&Ss[(warp * 16) * 132 + n * 16],
                                        sacc[n], 132, wmma::mem_row_major);
        }
        // Prefetch next K into the other buffer (own reads done; other warps
        // read buf i, prefetch targets buf i^1 — no barrier needed).
        if (have_next) { ATTN_LOAD_K(kt + 128, bufi ^ 1); }
        CP_COMMIT();
        __syncwarp();

        // Warp-local softmax: 2 lanes per row, 64 cols each (log2 domain).
        {
            float* srow = &Ss[r_sm * 132 + chalf * 64];
            float mx = -1e30f;
            float4 vv[16];
            #pragma unroll
            for (int i2 = 0; i2 < 16; i2++) {
                vv[i2] = ((float4*)srow)[i2];
                mx = fmaxf(mx, fmaxf(fmaxf(vv[i2].x, vv[i2].y), fmaxf(vv[i2].z, vv[i2].w)));
            }
            mx = fmaxf(mx, __shfl_xor_sync(0xffffffffu, mx, 1));
            float mold = mrow[r_sm];
            float newm = fmaxf(mold, mx);
            float f = exp2f(mold - newm);
            float sum = 0.f;
            unsigned int* prow = (unsigned int*)&Psh[r_sm * 136 + chalf * 64];
            #pragma unroll
            for (int i2 = 0; i2 < 16; i2++) {
                __half2 a0 = __floats2half2_rn(vv[i2].x - newm, vv[i2].y - newm);
                __half2 a1 = __floats2half2_rn(vv[i2].z - newm, vv[i2].w - newm);
                unsigned int p0 = h2exp2_bits(*(unsigned int*)&a0);
                unsigned int p1 = h2exp2_bits(*(unsigned int*)&a1);
                prow[2 * i2]     = p0;
                prow[2 * i2 + 1] = p1;
                float2 f0 = __half22float2(*(__half2*)&p0);
                float2 f1 = __half22float2(*(__half2*)&p1);
                sum += (f0.x + f0.y) + (f1.x + f1.y);
            }
            sum += __shfl_xor_sync(0xffffffffu, sum, 1);
            if (chalf == 0) { lrow[r_sm] = lrow[r_sm] * f + sum; mrow[r_sm] = newm; }
            if (f != 1.0f) {
                float* orow = &Os[r_sm * 132 + chalf * 64];
                #pragma unroll
                for (int i2 = 0; i2 < 16; i2++) {
                    float4 o = ((float4*)orow)[i2];
                    o.x *= f; o.y *= f; o.z *= f; o.w *= f;
                    ((float4*)orow)[i2] = o;
                }
            }
        }
        __syncwarp();

        // V(i) ready.
        if (have_next) { CP_WAIT(1); } else { CP_WAIT(0); }
        __syncthreads();

        // PV: warp-local O[16 x 128] += P[16 x 128] @ V[128 x 128].
        {
            wmma::fragment<wmma::matrix_a, 16, 16, 16, __half, wmma::row_major> pf[8];
            #pragma unroll
            for (int t = 0; t < 8; t++)
                wmma::load_matrix_sync(pf[t], &Psh[(warp * 16) * 136 + t * 16], 136);
            wmma::fragment<wmma::accumulator, 16, 16, 16, float> oacc[8];
            #pragma unroll
            for (int n = 0; n < 8; n++)
                wmma::load_matrix_sync(oacc[n], &Os[(warp * 16) * 132 + n * 16],
                                       132, wmma::mem_row_major);
            #pragma unroll
            for (int t = 0; t < 8; t++) {
                #pragma unroll
                for (int n = 0; n < 8; n++) {
                    wmma::fragment<wmma::matrix_b, 16, 16, 16, __half, wmma::row_major> bf;
                    wmma::load_matrix_sync(bf, &Vb[(t * 16) * 136 + n * 16], 136);
                    wmma::mma_sync(oacc[n], pf[t], bf, oacc[n]);
                }
            }
            #pragma unroll
            for (int n = 0; n < 8; n++)
                wmma::store_matrix_sync(&Os[(warp * 16) * 132 + n * 16],
                                        oacc[n], 132, wmma::mem_row_major);
        }
        // Prefetch next V into the other buffer.
        if (have_next) { ATTN_LOAD_V(kt + 128, bufi ^ 1); }
        CP_COMMIT();
    }

    __syncthreads();
    // Writeout: O / l -> half oj.
    #pragma unroll
    for (int it = 0; it < 16; it++) {
        int idx4 = tid + it * 128;
        int r = idx4 >> 5, c4 = idx4 & 31;
        float inv = 1.0f / lrow[r];
        float4 v = *(float4*)&Os[r * 132 + c4 * 4];
        size_t gaddr = ((size_t)(b * S_TOT + q0 + r)) * DIM_ + hd0 + c4 * 4;
        __half2* dst = (__half2*)&oj[gaddr];
        dst[0] = __floats2half2_rn(v.x * inv, v.y * inv);
        dst[1] = __floats2half2_rn(v.z * inv, v.w * inv);
    }
}

// ---------------------------------------------------------------------------
extern "C" void kernel_launch(void* const* d_in, const int* in_sizes, int n_in,
                              void* d_out, int out_size)
{
    const float* x    = (const float*)d_in[0];
    const float* ctx  = (const float*)d_in[1];
    const float* cosr = (const float*)d_in[2];
    const float* sinr = (const float*)d_in[3];
    const float* wq   = (const float*)d_in[4];
    const float* bq   = (const float*)d_in[5];
    const float* wk   = (const float*)d_in[6];
    const float* bk   = (const float*)d_in[7];
    const float* wv   = (const float*)d_in[8];
    const float* bv   = (const float*)d_in[9];
    const float* wqc  = (const float*)d_in[10];
    const float* bqc  = (const float*)d_in[11];
    const float* wkc  = (const float*)d_in[12];
    const float* bkc  = (const float*)d_in[13];
    const float* wvc  = (const float*)d_in[14];
    const float* bvc  = (const float*)d_in[15];
    const float* w_out     = (const float*)d_in[16];
    const float* b_out     = (const float*)d_in[17];
    const float* w_add_out = (const float*)d_in[18];
    const float* b_add_out = (const float*)d_in[19];
    const float* gq  = (const float*)d_in[20];
    const float* gk  = (const float*)d_in[21];
    const float* gqc = (const float*)d_in[22];
    const float* gkc = (const float*)d_in[23];
    float* out = (float*)d_out;

    __half *qj, *kj, *vj, *oj, *wr, *xr, *cr;
    cudaGetSymbolAddress((void**)&qj, g_qj);
    cudaGetSymbolAddress((void**)&kj, g_kj);
    cudaGetSymbolAddress((void**)&vj, g_vj);
    cudaGetSymbolAddress((void**)&oj, g_oj);
    cudaGetSymbolAddress((void**)&wr, g_wr);
    cudaGetSymbolAddress((void**)&xr, g_xr);
    cudaGetSymbolAddress((void**)&cr, g_cr);

    cudaFuncSetAttribute(gemm_fp16, cudaFuncAttributeMaxDynamicSharedMemorySize,
                         GEMM_SMEM_BYTES);
    cudaFuncSetAttribute(attn_kernel, cudaFuncAttributeMaxDynamicSharedMemorySize,
                         ATTN_SMEM_BYTES);

    // --- Pre-pass: round weights + activations to fp16 ---
    RoundSrc8 rs;
    rs.s[0] = wq;  rs.s[1] = wk;  rs.s[2] = wv;
    rs.s[3] = wqc; rs.s[4] = wkc; rs.s[5] = wvc;
    rs.s[6] = w_out; rs.s[7] = w_add_out;
    round_w_kernel<<<dim3(W_ELEMS / 4 / 256, 8), 256>>>(rs, wr);
    round_kernel<<<BATCH * 1024 * DIM_ / 4 / 256, 256>>>(x, xr);
    round_kernel<<<BATCH * 512 * DIM_ / 4 / 256, 256>>>(ctx, cr);

    // --- Merged QKV GEMMs ---
    GemmJobs6 qkv;
    qkv.j[0] = { xr, wr + 0 * (size_t)W_ELEMS, bq, qj, 2048, 2048, 0, 1024, 1536, 512, 16, 0 };
    qkv.j[1] = { xr, wr + 1 * (size_t)W_ELEMS, bk, kj, 2048, 2048, 0, 1024, 1536, 512, 16, 0 };
    qkv.j[2] = { xr, wr + 2 * (size_t)W_ELEMS, bv, vj, 2048, 2048, 0, 1024, 1536, 512, 16, 0 };
    qkv.j[3] = { cr, wr + 3 * (size_t)W_ELEMS, bqc, qj, 1024, 1024, 0, 512, 1536, 0, 8, 0 };
    qkv.j[4] = { cr, wr + 4 * (size_t)W_ELEMS, bkc, kj, 1024, 1024, 0, 512, 1536, 0, 8, 0 };
    qkv.j[5] = { cr, wr + 5 * (size_t)W_ELEMS, bvc, vj, 1024, 1024, 0, 512, 1536, 0, 8, 0 };
    gemm_fp16<<<dim3(12, 16, 6), 256, GEMM_SMEM_BYTES>>>(qkv);

    // --- RMS norm + RoPE ---
    rms_rope_kernel<<<dim3(S_TOT, BATCH, 2), dim3(128)>>>(qj, kj, cosr, sinr, gq, gk, gqc, gkc);

    // --- Attention v6 (warp-local, 128 threads) ---
    attn_kernel<<<dim3(S_TOT / 64, HEADS_, BATCH), 128, ATTN_SMEM_BYTES>>>(qj, kj, vj, oj);

    // --- Merged output projections ---
    GemmJobs6 outp;
    outp.j[0] = { oj, wr + 7 * (size_t)W_ELEMS, b_add_out, out,
                  512, 1536, 0, 1024, 1024, 0, 8, 1 };
    outp.j[1] = { oj, wr + 6 * (size_t)W_ELEMS, b_out, out + (size_t)BATCH * S_TXT_ * DIM_,
                  1024, 1536, 512, 2048, 2048, 0, 16, 1 };
    outp.j[2] = outp.j[0]; outp.j[3] = outp.j[0]; outp.j[4] = outp.j[0]; outp.j[5] = outp.j[0];
    gemm_fp16<<<dim3(12, 16, 2), 256, GEMM_SMEM_BYTES>>>(outp);
}